// round 9
// baseline (speedup 1.0000x reference)
#include <cuda_runtime.h>

#define N_MAX 100000
#define HID 64
#define V_MAX 16384

// ---- persistent scratch (no allocation allowed) ----
__device__ int    g_outdeg[N_MAX];
__device__ int    g_indeg[N_MAX];
__device__ float  g_nsrc[N_MAX];
__device__ float  g_ndst[N_MAX];
__device__ float  g_c0, g_c1, g_c2;
__device__ float  g_tdot[V_MAX];   // emb_table . (W0 W1 W2 wreg)
__device__ float2 g_P[N_MAX];      // prescaled (value, ones) pair
__device__ float2 g_A[N_MAX];      // float2 accumulator
__device__ float  g_Ps[N_MAX];     // prescaled scalar (final prop)
__device__ float  g_As[N_MAX];     // scalar accumulator (100k addrs)
__device__ float  g_s1[N_MAX];     // S^1 1

// vector RED (sm_90+)
#define RED2(addr, a, b) \
    asm volatile("red.global.add.v2.f32 [%0], {%1, %2};" \
                 :: "l"(addr), "f"(a), "f"(b) : "memory")

// ---------------------------------------------------------------
// shared helper: fold weights into smem vectors sa (W2.wreg), sb (W1.sa),
// sv (W0.sb). Runs in every block that needs them (deterministic, exact).
// ---------------------------------------------------------------
__device__ __forceinline__ void fold_smem(const float* __restrict__ Ws,
                                          const float* __restrict__ wreg,
                                          float* sa, float* sb, float* sv) {
    int k = threadIdx.x;
    if (k < HID) {
        float s = 0.f;
        #pragma unroll 8
        for (int j = 0; j < HID; j++) s += Ws[2 * HID * HID + k * HID + j] * wreg[j];
        sa[k] = s;
    }
    __syncthreads();
    if (k < HID) {
        float s = 0.f;
        #pragma unroll 8
        for (int j = 0; j < HID; j++) s += Ws[1 * HID * HID + k * HID + j] * sa[j];
        sb[k] = s;
    }
    __syncthreads();
    if (k < HID) {
        float s = 0.f;
        #pragma unroll 8
        for (int j = 0; j < HID; j++) s += Ws[0 * HID * HID + k * HID + j] * sb[j];
        sv[k] = s;
    }
    __syncthreads();
}

// ---------------------------------------------------------------
// K1 "pre": blocks [0, vB) compute tdot (with local fold);
//           blocks [vB, vB+nB) zero node arrays / out.
//           block 0 additionally writes c0,c1,c2.
// ---------------------------------------------------------------
__global__ void __launch_bounds__(256)
k_pre(const float* __restrict__ Ws, const float* __restrict__ bs,
      const float* __restrict__ wreg, const float* __restrict__ emb,
      float* out, int n, int ng, int vocab, int vB) {
    __shared__ float sa[HID], sb[HID], sv[HID];
    int b = blockIdx.x;

    if (b < vB) {
        fold_smem(Ws, wreg, sa, sb, sv);
        if (b == 0 && threadIdx.x == 0) {
            float c2 = 0.f, c1 = 0.f, c0 = 0.f;
            #pragma unroll 8
            for (int j = 0; j < HID; j++) {
                c2 += bs[2 * HID + j] * wreg[j];
                c1 += bs[1 * HID + j] * sa[j];
                c0 += bs[0 * HID + j] * sb[j];
            }
            g_c2 = c2; g_c1 = c1; g_c0 = c0;
        }
        // 16 lanes per vocab word
        int t = b * 256 + threadIdx.x;
        int w = t >> 4;
        int l = t & 15;
        if (w < vocab) {
            float4 ev = __ldg((const float4*)emb + w * 16 + l);
            float4 vv = *(const float4*)&sv[l * 4];
            float p = ev.x * vv.x + ev.y * vv.y + ev.z * vv.z + ev.w * vv.w;
            p += __shfl_xor_sync(0xffffffffu, p, 8);
            p += __shfl_xor_sync(0xffffffffu, p, 4);
            p += __shfl_xor_sync(0xffffffffu, p, 2);
            p += __shfl_xor_sync(0xffffffffu, p, 1);
            if (l == 0) g_tdot[w] = p;
        }
    } else {
        int i = (b - vB) * 256 + threadIdx.x;
        if (i < n) { g_outdeg[i] = 0; g_indeg[i] = 0; g_As[i] = 0.f; }
        if (i < ng) out[i] = 0.0f;
    }
}

// ---------------------------------------------------------------
// K2: degree counts, 8 edges/thread
// ---------------------------------------------------------------
__global__ void __launch_bounds__(256)
k_deg(const int* __restrict__ src, const int* __restrict__ dst, int e) {
    int i = (blockIdx.x * blockDim.x + threadIdx.x) * 8;
    if (i + 7 < e) {
        int4 s0 = *(const int4*)&src[i];
        int4 s1 = *(const int4*)&src[i + 4];
        int4 d0 = *(const int4*)&dst[i];
        int4 d1 = *(const int4*)&dst[i + 4];
        atomicAdd(&g_outdeg[s0.x], 1); atomicAdd(&g_outdeg[s0.y], 1);
        atomicAdd(&g_outdeg[s0.z], 1); atomicAdd(&g_outdeg[s0.w], 1);
        atomicAdd(&g_outdeg[s1.x], 1); atomicAdd(&g_outdeg[s1.y], 1);
        atomicAdd(&g_outdeg[s1.z], 1); atomicAdd(&g_outdeg[s1.w], 1);
        atomicAdd(&g_indeg[d0.x], 1);  atomicAdd(&g_indeg[d0.y], 1);
        atomicAdd(&g_indeg[d0.z], 1);  atomicAdd(&g_indeg[d0.w], 1);
        atomicAdd(&g_indeg[d1.x], 1);  atomicAdd(&g_indeg[d1.y], 1);
        atomicAdd(&g_indeg[d1.z], 1);  atomicAdd(&g_indeg[d1.w], 1);
    } else {
        for (; i < e; i++) {
            atomicAdd(&g_outdeg[src[i]], 1);
            atomicAdd(&g_indeg[dst[i]], 1);
        }
    }
}

// ---------------------------------------------------------------
// K3: norms + P0 = (z0, 1)*nsrc + zero A; 4 nodes/thread, int4 degree loads
// ---------------------------------------------------------------
__global__ void __launch_bounds__(256)
k_p0(const int* __restrict__ feats, int n) {
    int i = (blockIdx.x * blockDim.x + threadIdx.x) * 4;
    if (i >= n) return;
    if (i + 3 < n) {
        int4 od = *(const int4*)&g_outdeg[i];
        int4 id = *(const int4*)&g_indeg[i];
        int4 ft = *(const int4*)&feats[i];
        float ns0 = rsqrtf(fmaxf((float)od.x, 1.0f));
        float ns1 = rsqrtf(fmaxf((float)od.y, 1.0f));
        float ns2 = rsqrtf(fmaxf((float)od.z, 1.0f));
        float ns3 = rsqrtf(fmaxf((float)od.w, 1.0f));
        float nd0 = rsqrtf(fmaxf((float)id.x, 1.0f));
        float nd1 = rsqrtf(fmaxf((float)id.y, 1.0f));
        float nd2 = rsqrtf(fmaxf((float)id.z, 1.0f));
        float nd3 = rsqrtf(fmaxf((float)id.w, 1.0f));
        *(float4*)&g_nsrc[i] = make_float4(ns0, ns1, ns2, ns3);
        *(float4*)&g_ndst[i] = make_float4(nd0, nd1, nd2, nd3);
        float z0 = __ldg(&g_tdot[ft.x]);
        float z1 = __ldg(&g_tdot[ft.y]);
        float z2 = __ldg(&g_tdot[ft.z]);
        float z3 = __ldg(&g_tdot[ft.w]);
        g_P[i + 0] = make_float2(z0 * ns0, ns0);
        g_P[i + 1] = make_float2(z1 * ns1, ns1);
        g_P[i + 2] = make_float2(z2 * ns2, ns2);
        g_P[i + 3] = make_float2(z3 * ns3, ns3);
        float4 z4 = make_float4(0.f, 0.f, 0.f, 0.f);
        *(float4*)&g_A[i + 0] = z4;
        *(float4*)&g_A[i + 2] = z4;
    } else {
        for (; i < n; i++) {
            float ns = rsqrtf(fmaxf((float)g_outdeg[i], 1.0f));
            float nd = rsqrtf(fmaxf((float)g_indeg[i], 1.0f));
            g_nsrc[i] = ns;
            g_ndst[i] = nd;
            float z0 = __ldg(&g_tdot[feats[i]]);
            g_P[i] = make_float2(z0 * ns, ns);
            g_A[i] = make_float2(0.f, 0.f);
        }
    }
}

// ---------------------------------------------------------------
// K4: float2 scatter propagation via vector RED, 8 edges/thread
// ---------------------------------------------------------------
__global__ void __launch_bounds__(256)
k_prop2(const int* __restrict__ src, const int* __restrict__ dst, int e) {
    int i = (blockIdx.x * blockDim.x + threadIdx.x) * 8;
    if (i + 7 < e) {
        int4 s0 = *(const int4*)&src[i];
        int4 s1 = *(const int4*)&src[i + 4];
        int4 d0 = *(const int4*)&dst[i];
        int4 d1 = *(const int4*)&dst[i + 4];
        float2 p0 = __ldg(&g_P[s0.x]);
        float2 p1 = __ldg(&g_P[s0.y]);
        float2 p2 = __ldg(&g_P[s0.z]);
        float2 p3 = __ldg(&g_P[s0.w]);
        float2 p4 = __ldg(&g_P[s1.x]);
        float2 p5 = __ldg(&g_P[s1.y]);
        float2 p6 = __ldg(&g_P[s1.z]);
        float2 p7 = __ldg(&g_P[s1.w]);
        RED2(&g_A[d0.x], p0.x, p0.y);
        RED2(&g_A[d0.y], p1.x, p1.y);
        RED2(&g_A[d0.z], p2.x, p2.y);
        RED2(&g_A[d0.w], p3.x, p3.y);
        RED2(&g_A[d1.x], p4.x, p4.y);
        RED2(&g_A[d1.y], p5.x, p5.y);
        RED2(&g_A[d1.z], p6.x, p6.y);
        RED2(&g_A[d1.w], p7.x, p7.y);
    } else {
        for (; i < e; i++) {
            float2 p = __ldg(&g_P[src[i]]);
            RED2(&g_A[dst[i]], p.x, p.y);
        }
    }
}

// ---------------------------------------------------------------
// K5: rescale after prop1: s1 = A.y*nd; P = (A*nd)*ns; A = 0
// ---------------------------------------------------------------
__global__ void __launch_bounds__(256)
k_rescale1(int n) {
    int i = blockIdx.x * blockDim.x + threadIdx.x;
    if (i >= n) return;
    float2 A = g_A[i];
    float nd = g_ndst[i], ns = g_nsrc[i];
    float u = A.x * nd, ss = A.y * nd;
    g_s1[i] = ss;
    g_P[i] = make_float2(u * ns, ss * ns);
    g_A[i] = make_float2(0.f, 0.f);
}

// ---------------------------------------------------------------
// K6: rescale after prop2: Ps = A.x*nd*ns (s2 read later from A.y)
// ---------------------------------------------------------------
__global__ void __launch_bounds__(256)
k_rescale2(int n) {
    int i = blockIdx.x * blockDim.x + threadIdx.x;
    if (i >= n) return;
    g_Ps[i] = g_A[i].x * g_ndst[i] * g_nsrc[i];
}

// ---------------------------------------------------------------
// K7: final scalar prop: As[dst] += Ps[src], 8 edges/thread
// ---------------------------------------------------------------
__global__ void __launch_bounds__(256)
k_prop1(const int* __restrict__ src, const int* __restrict__ dst, int e) {
    int i = (blockIdx.x * blockDim.x + threadIdx.x) * 8;
    if (i + 7 < e) {
        int4 s0 = *(const int4*)&src[i];
        int4 s1 = *(const int4*)&src[i + 4];
        int4 d0 = *(const int4*)&dst[i];
        int4 d1 = *(const int4*)&dst[i + 4];
        atomicAdd(&g_As[d0.x], __ldg(&g_Ps[s0.x]));
        atomicAdd(&g_As[d0.y], __ldg(&g_Ps[s0.y]));
        atomicAdd(&g_As[d0.z], __ldg(&g_Ps[s0.z]));
        atomicAdd(&g_As[d0.w], __ldg(&g_Ps[s0.w]));
        atomicAdd(&g_As[d1.x], __ldg(&g_Ps[s1.x]));
        atomicAdd(&g_As[d1.y], __ldg(&g_Ps[s1.y]));
        atomicAdd(&g_As[d1.z], __ldg(&g_Ps[s1.z]));
        atomicAdd(&g_As[d1.w], __ldg(&g_Ps[s1.w]));
    } else {
        for (; i < e; i++)
            atomicAdd(&g_As[dst[i]], __ldg(&g_Ps[src[i]]));
    }
}

// ---------------------------------------------------------------
// K8: per-node combine + pooled output (s2 = A.y*nd inline)
// ---------------------------------------------------------------
__global__ void __launch_bounds__(256)
k_out(const int* __restrict__ gid, float* __restrict__ out, int n) {
    int i = blockIdx.x * blockDim.x + threadIdx.x;
    if (i >= n) return;
    float nd = g_ndst[i];
    float s2 = g_A[i].y * nd;
    float val = g_As[i] * nd + g_c0 * s2 + g_c1 * g_s1[i] + g_c2;
    atomicAdd(&out[gid[i]], val);
}

// ---------------------------------------------------------------
extern "C" void kernel_launch(void* const* d_in, const int* in_sizes, int n_in,
                              void* d_out, int out_size)
{
    const int* feats = (const int*)d_in[0];
    const int* src   = (const int*)d_in[1];
    const int* dst   = (const int*)d_in[2];
    const int* gid   = (const int*)d_in[3];
    int k = 4;
    if (n_in >= 9 && in_sizes[4] == 1) k = 5;
    const float* emb  = (const float*)d_in[k];
    const float* Ws   = (const float*)d_in[k + 1];
    const float* bs   = (const float*)d_in[k + 2];
    const float* wreg = (const float*)d_in[k + 3];
    float* out = (float*)d_out;

    int n = in_sizes[0];
    int e = in_sizes[1];
    int ng = out_size;
    int vocab = in_sizes[k] / HID;

    int nB = (n + 255) / 256;
    int vB = (vocab * 16 + 255) / 256;
    int eB = (e / 8 + 256) / 256;

    k_pre<<<vB + nB, 256>>>(Ws, bs, wreg, emb, out, n, ng, vocab, vB);
    k_deg<<<eB, 256>>>(src, dst, e);
    k_p0<<<(n / 4 + 256) / 256, 256>>>(feats, n);

    k_prop2<<<eB, 256>>>(src, dst, e);     // S^1
    k_rescale1<<<nB, 256>>>(n);
    k_prop2<<<eB, 256>>>(src, dst, e);     // S^2
    k_rescale2<<<nB, 256>>>(n);
    k_prop1<<<eB, 256>>>(src, dst, e);     // S^3 (scalar)
    k_out<<<nB, 256>>>(gid, out, n);
}

// round 10
// speedup vs baseline: 1.0528x; 1.0528x over previous
#include <cuda_runtime.h>

#define N_MAX 100000
#define HID 64
#define V_MAX 16384

// ---- persistent scratch (no allocation allowed) ----
__device__ int    g_outdeg[N_MAX];
__device__ int    g_indeg[N_MAX];
__device__ float  g_nsrc[N_MAX];
__device__ float  g_ndst[N_MAX];
__device__ float  g_v[HID];
__device__ float  g_c0, g_c1, g_c2;
__device__ float  g_tdot[V_MAX];
__device__ float2 g_P[N_MAX];
__device__ float2 g_A[N_MAX];
__device__ float  g_Ps[N_MAX];
__device__ float  g_As[N_MAX];
__device__ float  g_s1[N_MAX];

// grid barrier state (persists across launches; sense-relative)
__device__ volatile unsigned g_gen;
__device__ unsigned g_count;

#define RED2(addr, a, b) \
    asm volatile("red.global.add.v2.f32 [%0], {%1, %2};" \
                 :: "l"(addr), "f"(a), "f"(b) : "memory")

// ---------------------------------------------------------------
// software grid barrier — safe because grid <= co-resident capacity
// ---------------------------------------------------------------
__device__ __forceinline__ void gridbar(unsigned nb) {
    __syncthreads();
    if (threadIdx.x == 0) {
        unsigned old = g_gen;
        __threadfence();
        if (atomicAdd(&g_count, 1u) == nb - 1u) {
            g_count = 0u;
            __threadfence();
            g_gen = old + 1u;
        } else {
            while (g_gen == old) __nanosleep(64);
            __threadfence();
        }
    }
    __syncthreads();
}

// ---------------------------------------------------------------
// the whole GCN pipeline in one persistent kernel
// ---------------------------------------------------------------
__global__ void __launch_bounds__(256, 8)
k_persist(const int* __restrict__ feats, const int* __restrict__ src,
          const int* __restrict__ dst, const int* __restrict__ gid,
          const float* __restrict__ emb, const float* __restrict__ Ws,
          const float* __restrict__ bs, const float* __restrict__ wreg,
          float* __restrict__ out,
          int n, int e, int ng, int vocab)
{
    const unsigned nb  = gridDim.x;
    const int      nt  = gridDim.x * 256;
    const int      gt  = blockIdx.x * 256 + threadIdx.x;
    __shared__ float sa[HID], sb[HID];

    // ---------- Phase A: zero arrays + fold weights (block 0) ----------
    for (int i = gt; i < n; i += nt) { g_outdeg[i] = 0; g_indeg[i] = 0; g_As[i] = 0.f; }
    for (int i = gt; i < ng; i += nt) out[i] = 0.0f;
    if (blockIdx.x == 0) {
        int k = threadIdx.x;
        if (k < HID) {
            float s = 0.f;
            #pragma unroll 8
            for (int j = 0; j < HID; j++) s += Ws[2 * HID * HID + k * HID + j] * wreg[j];
            sa[k] = s;
        }
        __syncthreads();
        if (k < HID) {
            float s = 0.f;
            #pragma unroll 8
            for (int j = 0; j < HID; j++) s += Ws[1 * HID * HID + k * HID + j] * sa[j];
            sb[k] = s;
        }
        __syncthreads();
        if (k < HID) {
            float s = 0.f;
            #pragma unroll 8
            for (int j = 0; j < HID; j++) s += Ws[0 * HID * HID + k * HID + j] * sb[j];
            g_v[k] = s;
        }
        if (k == 0) {
            float c2 = 0.f, c1 = 0.f, c0 = 0.f;
            #pragma unroll 8
            for (int j = 0; j < HID; j++) {
                c2 += bs[2 * HID + j] * wreg[j];
                c1 += bs[1 * HID + j] * sa[j];
                c0 += bs[0 * HID + j] * sb[j];
            }
            g_c2 = c2; g_c1 = c1; g_c0 = c0;
        }
    }
    gridbar(nb);

    // ---------- Phase B: degree counts + tdot ----------
    {
        int e4 = e >> 2;
        for (int j = gt; j < e4; j += nt) {
            int4 s4 = __ldg((const int4*)src + j);
            int4 d4 = __ldg((const int4*)dst + j);
            atomicAdd(&g_outdeg[s4.x], 1); atomicAdd(&g_outdeg[s4.y], 1);
            atomicAdd(&g_outdeg[s4.z], 1); atomicAdd(&g_outdeg[s4.w], 1);
            atomicAdd(&g_indeg[d4.x], 1);  atomicAdd(&g_indeg[d4.y], 1);
            atomicAdd(&g_indeg[d4.z], 1);  atomicAdd(&g_indeg[d4.w], 1);
        }
        for (int i = (e4 << 2) + gt; i < e; i += nt) {
            atomicAdd(&g_outdeg[src[i]], 1);
            atomicAdd(&g_indeg[dst[i]], 1);
        }
        // tdot: 16 lanes per vocab word
        for (int t = gt; t < vocab * 16; t += nt) {
            int w = t >> 4, l = t & 15;
            float4 ev = __ldg((const float4*)emb + w * 16 + l);
            float4 vv = *(const float4*)&g_v[l * 4];
            float p = ev.x * vv.x + ev.y * vv.y + ev.z * vv.z + ev.w * vv.w;
            p += __shfl_xor_sync(0xffffffffu, p, 8);
            p += __shfl_xor_sync(0xffffffffu, p, 4);
            p += __shfl_xor_sync(0xffffffffu, p, 2);
            p += __shfl_xor_sync(0xffffffffu, p, 1);
            if (l == 0) g_tdot[w] = p;
        }
    }
    gridbar(nb);

    // ---------- Phase C: norms + P0 + zero A ----------
    for (int i = gt; i < n; i += nt) {
        float ns = rsqrtf(fmaxf((float)g_outdeg[i], 1.0f));
        float nd = rsqrtf(fmaxf((float)g_indeg[i], 1.0f));
        g_nsrc[i] = ns;
        g_ndst[i] = nd;
        float z0 = __ldg(&g_tdot[feats[i]]);
        g_P[i] = make_float2(z0 * ns, ns);
        g_A[i] = make_float2(0.f, 0.f);
    }
    gridbar(nb);

    // ---------- Phase D: prop S^1 (float2 RED) ----------
    {
        int e4 = e >> 2;
        for (int j = gt; j < e4; j += nt) {
            int4 s4 = __ldg((const int4*)src + j);
            int4 d4 = __ldg((const int4*)dst + j);
            float2 p0 = __ldg(&g_P[s4.x]);
            float2 p1 = __ldg(&g_P[s4.y]);
            float2 p2 = __ldg(&g_P[s4.z]);
            float2 p3 = __ldg(&g_P[s4.w]);
            RED2(&g_A[d4.x], p0.x, p0.y);
            RED2(&g_A[d4.y], p1.x, p1.y);
            RED2(&g_A[d4.z], p2.x, p2.y);
            RED2(&g_A[d4.w], p3.x, p3.y);
        }
        for (int i = (e4 << 2) + gt; i < e; i += nt) {
            float2 p = __ldg(&g_P[src[i]]);
            RED2(&g_A[dst[i]], p.x, p.y);
        }
    }
    gridbar(nb);

    // ---------- Phase E: rescale1 ----------
    for (int i = gt; i < n; i += nt) {
        float2 A = g_A[i];
        float nd = g_ndst[i], ns = g_nsrc[i];
        float u = A.x * nd, ss = A.y * nd;
        g_s1[i] = ss;
        g_P[i] = make_float2(u * ns, ss * ns);
        g_A[i] = make_float2(0.f, 0.f);
    }
    gridbar(nb);

    // ---------- Phase F: prop S^2 ----------
    {
        int e4 = e >> 2;
        for (int j = gt; j < e4; j += nt) {
            int4 s4 = __ldg((const int4*)src + j);
            int4 d4 = __ldg((const int4*)dst + j);
            float2 p0 = __ldg(&g_P[s4.x]);
            float2 p1 = __ldg(&g_P[s4.y]);
            float2 p2 = __ldg(&g_P[s4.z]);
            float2 p3 = __ldg(&g_P[s4.w]);
            RED2(&g_A[d4.x], p0.x, p0.y);
            RED2(&g_A[d4.y], p1.x, p1.y);
            RED2(&g_A[d4.z], p2.x, p2.y);
            RED2(&g_A[d4.w], p3.x, p3.y);
        }
        for (int i = (e4 << 2) + gt; i < e; i += nt) {
            float2 p = __ldg(&g_P[src[i]]);
            RED2(&g_A[dst[i]], p.x, p.y);
        }
    }
    gridbar(nb);

    // ---------- Phase G: rescale2 (Ps only; s2 read from A.y later) ----------
    for (int i = gt; i < n; i += nt)
        g_Ps[i] = g_A[i].x * g_ndst[i] * g_nsrc[i];
    gridbar(nb);

    // ---------- Phase H: prop S^3 (scalar) ----------
    {
        int e4 = e >> 2;
        for (int j = gt; j < e4; j += nt) {
            int4 s4 = __ldg((const int4*)src + j);
            int4 d4 = __ldg((const int4*)dst + j);
            atomicAdd(&g_As[d4.x], __ldg(&g_Ps[s4.x]));
            atomicAdd(&g_As[d4.y], __ldg(&g_Ps[s4.y]));
            atomicAdd(&g_As[d4.z], __ldg(&g_Ps[s4.z]));
            atomicAdd(&g_As[d4.w], __ldg(&g_Ps[s4.w]));
        }
        for (int i = (e4 << 2) + gt; i < e; i += nt)
            atomicAdd(&g_As[dst[i]], __ldg(&g_Ps[src[i]]));
    }
    gridbar(nb);

    // ---------- Phase I: combine + pooled output ----------
    for (int i = gt; i < n; i += nt) {
        float nd = g_ndst[i];
        float s2 = g_A[i].y * nd;
        float val = g_As[i] * nd + g_c0 * s2 + g_c1 * g_s1[i] + g_c2;
        atomicAdd(&out[gid[i]], val);
    }
}

// ---------------------------------------------------------------
extern "C" void kernel_launch(void* const* d_in, const int* in_sizes, int n_in,
                              void* d_out, int out_size)
{
    const int* feats = (const int*)d_in[0];
    const int* src   = (const int*)d_in[1];
    const int* dst   = (const int*)d_in[2];
    const int* gid   = (const int*)d_in[3];
    int k = 4;
    if (n_in >= 9 && in_sizes[4] == 1) k = 5;
    const float* emb  = (const float*)d_in[k];
    const float* Ws   = (const float*)d_in[k + 1];
    const float* bs   = (const float*)d_in[k + 2];
    const float* wreg = (const float*)d_in[k + 3];
    float* out = (float*)d_out;

    int n = in_sizes[0];
    int e = in_sizes[1];
    int ng = out_size;
    int vocab = in_sizes[k] / HID;

    // size grid to guaranteed co-residency (software barrier safety)
    int dev = 0;
    cudaGetDevice(&dev);
    int nsm = 0;
    cudaDeviceGetAttribute(&nsm, cudaDevAttrMultiProcessorCount, dev);
    int bpm = 0;
    cudaOccupancyMaxActiveBlocksPerMultiprocessor(&bpm, k_persist, 256, 0);
    if (bpm < 1) bpm = 1;
    int grid = nsm * bpm;
    if (grid < 1) grid = 148;

    k_persist<<<grid, 256>>>(feats, src, dst, gid, emb, Ws, bs, wreg,
                             out, n, e, ng, vocab);
}

// round 11
// speedup vs baseline: 1.0997x; 1.0445x over previous
#include <cuda_runtime.h>

#define N_MAX 100000
#define HID 64
#define V_MAX 16384

// ---- persistent scratch (no allocation allowed) ----
__device__ int    g_outdeg[N_MAX];
__device__ int    g_indeg[N_MAX];
__device__ float  g_nsrc[N_MAX];
__device__ float  g_ndst[N_MAX];
__device__ float  g_c0, g_c1, g_c2;
__device__ float  g_tdot[V_MAX];
__device__ float2 g_P[N_MAX];
__device__ float2 g_A[N_MAX];
__device__ float  g_Ps[N_MAX];
__device__ float  g_As[N_MAX];
__device__ float  g_s1[N_MAX];

#define RED2(addr, a, b) \
    asm volatile("red.global.add.v2.f32 [%0], {%1, %2};" \
                 :: "l"(addr), "f"(a), "f"(b) : "memory")

// ---------------------------------------------------------------
// K1 "pre": blocks [0,vB) fold weights locally + compute tdot;
//           blocks [vB,..) zero node arrays / out. No dependency.
// ---------------------------------------------------------------
__global__ void __launch_bounds__(256)
k_pre(const float* __restrict__ Ws, const float* __restrict__ bs,
      const float* __restrict__ wreg, const float* __restrict__ emb,
      float* out, int n, int ng, int vocab, int vB) {
    __shared__ float sa[HID], sb[HID], sv[HID];
    int b = blockIdx.x;

    if (b < vB) {
        int k = threadIdx.x;
        if (k < HID) {
            float s = 0.f;
            #pragma unroll 8
            for (int j = 0; j < HID; j++) s += Ws[2 * HID * HID + k * HID + j] * wreg[j];
            sa[k] = s;
        }
        __syncthreads();
        if (k < HID) {
            float s = 0.f;
            #pragma unroll 8
            for (int j = 0; j < HID; j++) s += Ws[1 * HID * HID + k * HID + j] * sa[j];
            sb[k] = s;
        }
        __syncthreads();
        if (k < HID) {
            float s = 0.f;
            #pragma unroll 8
            for (int j = 0; j < HID; j++) s += Ws[0 * HID * HID + k * HID + j] * sb[j];
            sv[k] = s;
        }
        __syncthreads();
        if (b == 0 && k == 0) {
            float c2 = 0.f, c1 = 0.f, c0 = 0.f;
            #pragma unroll 8
            for (int j = 0; j < HID; j++) {
                c2 += bs[2 * HID + j] * wreg[j];
                c1 += bs[1 * HID + j] * sa[j];
                c0 += bs[0 * HID + j] * sb[j];
            }
            g_c2 = c2; g_c1 = c1; g_c0 = c0;
        }
        int t = b * 256 + threadIdx.x;
        int w = t >> 4;
        int l = t & 15;
        if (w < vocab) {
            float4 ev = __ldg((const float4*)emb + w * 16 + l);
            float4 vv = *(const float4*)&sv[l * 4];
            float p = ev.x * vv.x + ev.y * vv.y + ev.z * vv.z + ev.w * vv.w;
            p += __shfl_xor_sync(0xffffffffu, p, 8);
            p += __shfl_xor_sync(0xffffffffu, p, 4);
            p += __shfl_xor_sync(0xffffffffu, p, 2);
            p += __shfl_xor_sync(0xffffffffu, p, 1);
            if (l == 0) g_tdot[w] = p;
        }
    } else {
        int i = (b - vB) * 256 + threadIdx.x;
        if (i < n) { g_outdeg[i] = 0; g_indeg[i] = 0; g_As[i] = 0.f; }
        if (i < ng) out[i] = 0.0f;
    }
    cudaTriggerProgrammaticLaunchCompletion();
}

// ---------------------------------------------------------------
// K2: degree counts, 4 edges/thread (full residency grid)
// ---------------------------------------------------------------
__global__ void __launch_bounds__(256)
k_deg(const int* __restrict__ src, const int* __restrict__ dst, int e) {
    int i = (blockIdx.x * 256 + threadIdx.x) * 4;
    int4 s4, d4;
    bool full = (i + 3 < e);
    if (full) {                      // prefetch read-only inputs pre-sync
        s4 = __ldg((const int4*)(src + i));
        d4 = __ldg((const int4*)(dst + i));
    }
    cudaGridDependencySynchronize();  // wait: arrays zeroed
    if (full) {
        atomicAdd(&g_outdeg[s4.x], 1); atomicAdd(&g_outdeg[s4.y], 1);
        atomicAdd(&g_outdeg[s4.z], 1); atomicAdd(&g_outdeg[s4.w], 1);
        atomicAdd(&g_indeg[d4.x], 1);  atomicAdd(&g_indeg[d4.y], 1);
        atomicAdd(&g_indeg[d4.z], 1);  atomicAdd(&g_indeg[d4.w], 1);
    } else {
        for (; i < e; i++) {
            atomicAdd(&g_outdeg[src[i]], 1);
            atomicAdd(&g_indeg[dst[i]], 1);
        }
    }
    cudaTriggerProgrammaticLaunchCompletion();
}

// ---------------------------------------------------------------
// K3: norms + P0 + zero A; 4 nodes/thread
// ---------------------------------------------------------------
__global__ void __launch_bounds__(256)
k_p0(const int* __restrict__ feats, int n) {
    int i = (blockIdx.x * 256 + threadIdx.x) * 4;
    int4 ft;
    bool full = (i + 3 < n);
    if (full) ft = __ldg((const int4*)(feats + i));   // input prefetch
    cudaGridDependencySynchronize();  // wait: degrees + tdot
    if (full) {
        int4 od = *(const int4*)&g_outdeg[i];
        int4 id = *(const int4*)&g_indeg[i];
        float ns0 = rsqrtf(fmaxf((float)od.x, 1.0f));
        float ns1 = rsqrtf(fmaxf((float)od.y, 1.0f));
        float ns2 = rsqrtf(fmaxf((float)od.z, 1.0f));
        float ns3 = rsqrtf(fmaxf((float)od.w, 1.0f));
        float nd0 = rsqrtf(fmaxf((float)id.x, 1.0f));
        float nd1 = rsqrtf(fmaxf((float)id.y, 1.0f));
        float nd2 = rsqrtf(fmaxf((float)id.z, 1.0f));
        float nd3 = rsqrtf(fmaxf((float)id.w, 1.0f));
        *(float4*)&g_nsrc[i] = make_float4(ns0, ns1, ns2, ns3);
        *(float4*)&g_ndst[i] = make_float4(nd0, nd1, nd2, nd3);
        float z0 = __ldg(&g_tdot[ft.x]);
        float z1 = __ldg(&g_tdot[ft.y]);
        float z2 = __ldg(&g_tdot[ft.z]);
        float z3 = __ldg(&g_tdot[ft.w]);
        g_P[i + 0] = make_float2(z0 * ns0, ns0);
        g_P[i + 1] = make_float2(z1 * ns1, ns1);
        g_P[i + 2] = make_float2(z2 * ns2, ns2);
        g_P[i + 3] = make_float2(z3 * ns3, ns3);
        float4 z4 = make_float4(0.f, 0.f, 0.f, 0.f);
        *(float4*)&g_A[i + 0] = z4;
        *(float4*)&g_A[i + 2] = z4;
    } else {
        for (; i < n; i++) {
            float ns = rsqrtf(fmaxf((float)g_outdeg[i], 1.0f));
            float nd = rsqrtf(fmaxf((float)g_indeg[i], 1.0f));
            g_nsrc[i] = ns;
            g_ndst[i] = nd;
            float z0 = __ldg(&g_tdot[feats[i]]);
            g_P[i] = make_float2(z0 * ns, ns);
            g_A[i] = make_float2(0.f, 0.f);
        }
    }
    cudaTriggerProgrammaticLaunchCompletion();
}

// ---------------------------------------------------------------
// K4/K6: float2 scatter propagation via vector RED, 4 edges/thread
// ---------------------------------------------------------------
__global__ void __launch_bounds__(256)
k_prop2(const int* __restrict__ src, const int* __restrict__ dst, int e) {
    int i = (blockIdx.x * 256 + threadIdx.x) * 4;
    int4 s4, d4;
    bool full = (i + 3 < e);
    if (full) {
        s4 = __ldg((const int4*)(src + i));
        d4 = __ldg((const int4*)(dst + i));
    }
    cudaGridDependencySynchronize();  // wait: P ready, A zeroed
    if (full) {
        float2 p0 = __ldg(&g_P[s4.x]);
        float2 p1 = __ldg(&g_P[s4.y]);
        float2 p2 = __ldg(&g_P[s4.z]);
        float2 p3 = __ldg(&g_P[s4.w]);
        RED2(&g_A[d4.x], p0.x, p0.y);
        RED2(&g_A[d4.y], p1.x, p1.y);
        RED2(&g_A[d4.z], p2.x, p2.y);
        RED2(&g_A[d4.w], p3.x, p3.y);
    } else {
        for (; i < e; i++) {
            float2 p = __ldg(&g_P[src[i]]);
            RED2(&g_A[dst[i]], p.x, p.y);
        }
    }
    cudaTriggerProgrammaticLaunchCompletion();
}

// ---------------------------------------------------------------
// K5: rescale1: s1 = A.y*nd; P = (A*nd)*ns; A = 0
// ---------------------------------------------------------------
__global__ void __launch_bounds__(256)
k_rescale1(int n) {
    int i = blockIdx.x * 256 + threadIdx.x;
    cudaGridDependencySynchronize();
    if (i < n) {
        float2 A = g_A[i];
        float nd = g_ndst[i], ns = g_nsrc[i];
        float u = A.x * nd, ss = A.y * nd;
        g_s1[i] = ss;
        g_P[i] = make_float2(u * ns, ss * ns);
        g_A[i] = make_float2(0.f, 0.f);
    }
    cudaTriggerProgrammaticLaunchCompletion();
}

// ---------------------------------------------------------------
// K7: rescale2: Ps = A.x*nd*ns (s2 read later from A.y)
// ---------------------------------------------------------------
__global__ void __launch_bounds__(256)
k_rescale2(int n) {
    int i = blockIdx.x * 256 + threadIdx.x;
    cudaGridDependencySynchronize();
    if (i < n)
        g_Ps[i] = g_A[i].x * g_ndst[i] * g_nsrc[i];
    cudaTriggerProgrammaticLaunchCompletion();
}

// ---------------------------------------------------------------
// K8: final scalar prop: As[dst] += Ps[src], 4 edges/thread
// ---------------------------------------------------------------
__global__ void __launch_bounds__(256)
k_prop1(const int* __restrict__ src, const int* __restrict__ dst, int e) {
    int i = (blockIdx.x * 256 + threadIdx.x) * 4;
    int4 s4, d4;
    bool full = (i + 3 < e);
    if (full) {
        s4 = __ldg((const int4*)(src + i));
        d4 = __ldg((const int4*)(dst + i));
    }
    cudaGridDependencySynchronize();
    if (full) {
        atomicAdd(&g_As[d4.x], __ldg(&g_Ps[s4.x]));
        atomicAdd(&g_As[d4.y], __ldg(&g_Ps[s4.y]));
        atomicAdd(&g_As[d4.z], __ldg(&g_Ps[s4.z]));
        atomicAdd(&g_As[d4.w], __ldg(&g_Ps[s4.w]));
    } else {
        for (; i < e; i++)
            atomicAdd(&g_As[dst[i]], __ldg(&g_Ps[src[i]]));
    }
    cudaTriggerProgrammaticLaunchCompletion();
}

// ---------------------------------------------------------------
// K9: per-node combine + pooled output
// ---------------------------------------------------------------
__global__ void __launch_bounds__(256)
k_out(const int* __restrict__ gid, float* __restrict__ out, int n) {
    int i = blockIdx.x * 256 + threadIdx.x;
    int g = (i < n) ? __ldg(&gid[i]) : 0;     // input prefetch
    cudaGridDependencySynchronize();
    if (i < n) {
        float nd = g_ndst[i];
        float s2 = g_A[i].y * nd;
        float val = g_As[i] * nd + g_c0 * s2 + g_c1 * g_s1[i] + g_c2;
        atomicAdd(&out[g], val);
    }
}

// ---------------------------------------------------------------
// PDL launch helper (programmatic stream serialization)
// ---------------------------------------------------------------
template <typename F, typename... Args>
static inline void launch_pdl(F kern, int grid, bool pdl, Args... args) {
    cudaLaunchConfig_t cfg = {};
    cfg.gridDim = dim3(grid, 1, 1);
    cfg.blockDim = dim3(256, 1, 1);
    cfg.dynamicSmemBytes = 0;
    cfg.stream = 0;
    cudaLaunchAttribute attr[1];
    attr[0].id = cudaLaunchAttributeProgrammaticStreamSerialization;
    attr[0].val.programmaticStreamSerializationAllowed = 1;
    cfg.attrs = attr;
    cfg.numAttrs = pdl ? 1 : 0;
    cudaLaunchKernelEx(&cfg, kern, args...);
}

// ---------------------------------------------------------------
extern "C" void kernel_launch(void* const* d_in, const int* in_sizes, int n_in,
                              void* d_out, int out_size)
{
    const int* feats = (const int*)d_in[0];
    const int* src   = (const int*)d_in[1];
    const int* dst   = (const int*)d_in[2];
    const int* gid   = (const int*)d_in[3];
    int k = 4;
    if (n_in >= 9 && in_sizes[4] == 1) k = 5;
    const float* emb  = (const float*)d_in[k];
    const float* Ws   = (const float*)d_in[k + 1];
    const float* bs   = (const float*)d_in[k + 2];
    const float* wreg = (const float*)d_in[k + 3];
    float* out = (float*)d_out;

    int n = in_sizes[0];
    int e = in_sizes[1];
    int ng = out_size;
    int vocab = in_sizes[k] / HID;

    int nB = (n + 255) / 256;
    int vB = (vocab * 16 + 255) / 256;
    int eB = (e / 4 + 255) / 256;
    int pB = (n / 4 + 255) / 256;

    launch_pdl(k_pre, vB + nB, false, Ws, bs, wreg, emb, out, n, ng, vocab, vB);
    launch_pdl(k_deg, eB, true, src, dst, e);
    launch_pdl(k_p0, pB, true, feats, n);
    launch_pdl(k_prop2, eB, true, src, dst, e);      // S^1
    launch_pdl(k_rescale1, nB, true, n);
    launch_pdl(k_prop2, eB, true, src, dst, e);      // S^2
    launch_pdl(k_rescale2, nB, true, n);
    launch_pdl(k_prop1, eB, true, src, dst, e);      // S^3
    launch_pdl(k_out, nB, true, gid, out, n);
}

// round 12
// speedup vs baseline: 1.2673x; 1.1524x over previous
#include <cuda_runtime.h>

#define N_MAX 100000
#define HID 64
#define V_MAX 16384

// ---- persistent scratch (no allocation allowed) ----
__device__ int    g_outdeg[N_MAX];
__device__ int    g_indeg[N_MAX];
__device__ float  g_nsrc[N_MAX];
__device__ float  g_ndst[N_MAX];
__device__ float  g_v[HID];        // W0 W1 W2 wreg
__device__ float  g_c0, g_c1, g_c2;
__device__ float  g_tdot[V_MAX];   // emb_table . v
__device__ float2 g_P[N_MAX];      // prescaled (value, ones) pair
__device__ float2 g_A[N_MAX];      // float2 accumulator
__device__ float  g_Ps[N_MAX];     // prescaled scalar (final prop)
__device__ float  g_As[N_MAX];     // scalar accumulator (100k addrs)
__device__ float  g_s1[N_MAX];     // S^1 1

// vector RED (sm_90+)
#define RED2(addr, a, b) \
    asm volatile("red.global.add.v2.f32 [%0], {%1, %2};" \
                 :: "l"(addr), "f"(a), "f"(b) : "memory")

// ---------------------------------------------------------------
// K1: init + fold. Block 0 folds weights into g_v and bias scalars.
// ---------------------------------------------------------------
__global__ void k_init_fold(const float* __restrict__ Ws, const float* __restrict__ bs,
                            const float* __restrict__ wreg,
                            float* out, int n, int ng) {
    int i = blockIdx.x * blockDim.x + threadIdx.x;
    if (i < n) { g_outdeg[i] = 0; g_indeg[i] = 0; g_As[i] = 0.f; }
    if (i < ng) out[i] = 0.0f;

    if (blockIdx.x == 0) {
        __shared__ float sa[HID], sb[HID];
        int k = threadIdx.x;
        if (k < HID) {
            float s = 0.f;
            #pragma unroll 8
            for (int j = 0; j < HID; j++) s += Ws[2 * HID * HID + k * HID + j] * wreg[j];
            sa[k] = s;
        }
        __syncthreads();
        if (k < HID) {
            float s = 0.f;
            #pragma unroll 8
            for (int j = 0; j < HID; j++) s += Ws[1 * HID * HID + k * HID + j] * sa[j];
            sb[k] = s;
        }
        __syncthreads();
        if (k < HID) {
            float s = 0.f;
            #pragma unroll 8
            for (int j = 0; j < HID; j++) s += Ws[0 * HID * HID + k * HID + j] * sb[j];
            g_v[k] = s;
        }
        if (k == 0) {
            float c2 = 0.f, c1 = 0.f, c0 = 0.f;
            #pragma unroll 8
            for (int j = 0; j < HID; j++) {
                c2 += bs[2 * HID + j] * wreg[j];
                c1 += bs[1 * HID + j] * sa[j];
                c0 += bs[0 * HID + j] * sb[j];
            }
            g_c2 = c2; g_c1 = c1; g_c0 = c0;
        }
    }
}

// ---------------------------------------------------------------
// K2: degree counts (4 edges/thread) + tdot fused in
//     (tdot threads overlap with atomic-latency-bound degree work)
// ---------------------------------------------------------------
__global__ void k_deg_tdot(const int* __restrict__ src, const int* __restrict__ dst,
                           const float* __restrict__ emb, int e, int vocab) {
    int t = blockIdx.x * blockDim.x + threadIdx.x;

    // tdot: 16 lanes per vocab word, first vocab*16 threads
    if (t < vocab * 16) {
        int w = t >> 4;
        int l = t & 15;
        float4 ev = __ldg((const float4*)emb + w * 16 + l);
        float4 vv = *(const float4*)&g_v[l * 4];
        float p = ev.x * vv.x + ev.y * vv.y + ev.z * vv.z + ev.w * vv.w;
        p += __shfl_xor_sync(0xffffffffu, p, 8);
        p += __shfl_xor_sync(0xffffffffu, p, 4);
        p += __shfl_xor_sync(0xffffffffu, p, 2);
        p += __shfl_xor_sync(0xffffffffu, p, 1);
        if (l == 0) g_tdot[w] = p;
    }

    int i = t * 4;
    if (i + 3 < e) {
        int4 s = *(const int4*)&src[i];
        int4 d = *(const int4*)&dst[i];
        atomicAdd(&g_outdeg[s.x], 1); atomicAdd(&g_outdeg[s.y], 1);
        atomicAdd(&g_outdeg[s.z], 1); atomicAdd(&g_outdeg[s.w], 1);
        atomicAdd(&g_indeg[d.x], 1);  atomicAdd(&g_indeg[d.y], 1);
        atomicAdd(&g_indeg[d.z], 1);  atomicAdd(&g_indeg[d.w], 1);
    } else {
        for (; i < e; i++) {
            atomicAdd(&g_outdeg[src[i]], 1);
            atomicAdd(&g_indeg[dst[i]], 1);
        }
    }
}

// ---------------------------------------------------------------
// K3: norms + P0 = (z0, 1)*nsrc + zero A; 4 nodes/thread
// ---------------------------------------------------------------
__global__ void __launch_bounds__(256)
k_p0(const int* __restrict__ feats, int n) {
    int i = (blockIdx.x * blockDim.x + threadIdx.x) * 4;
    if (i >= n) return;
    if (i + 3 < n) {
        int4 od = *(const int4*)&g_outdeg[i];
        int4 id = *(const int4*)&g_indeg[i];
        int4 ft = *(const int4*)&feats[i];
        float ns0 = rsqrtf(fmaxf((float)od.x, 1.0f));
        float ns1 = rsqrtf(fmaxf((float)od.y, 1.0f));
        float ns2 = rsqrtf(fmaxf((float)od.z, 1.0f));
        float ns3 = rsqrtf(fmaxf((float)od.w, 1.0f));
        float nd0 = rsqrtf(fmaxf((float)id.x, 1.0f));
        float nd1 = rsqrtf(fmaxf((float)id.y, 1.0f));
        float nd2 = rsqrtf(fmaxf((float)id.z, 1.0f));
        float nd3 = rsqrtf(fmaxf((float)id.w, 1.0f));
        *(float4*)&g_nsrc[i] = make_float4(ns0, ns1, ns2, ns3);
        *(float4*)&g_ndst[i] = make_float4(nd0, nd1, nd2, nd3);
        float z0 = __ldg(&g_tdot[ft.x]);
        float z1 = __ldg(&g_tdot[ft.y]);
        float z2 = __ldg(&g_tdot[ft.z]);
        float z3 = __ldg(&g_tdot[ft.w]);
        g_P[i + 0] = make_float2(z0 * ns0, ns0);
        g_P[i + 1] = make_float2(z1 * ns1, ns1);
        g_P[i + 2] = make_float2(z2 * ns2, ns2);
        g_P[i + 3] = make_float2(z3 * ns3, ns3);
        float4 z4 = make_float4(0.f, 0.f, 0.f, 0.f);
        *(float4*)&g_A[i + 0] = z4;
        *(float4*)&g_A[i + 2] = z4;
    } else {
        for (; i < n; i++) {
            float ns = rsqrtf(fmaxf((float)g_outdeg[i], 1.0f));
            float nd = rsqrtf(fmaxf((float)g_indeg[i], 1.0f));
            g_nsrc[i] = ns;
            g_ndst[i] = nd;
            float z0 = __ldg(&g_tdot[feats[i]]);
            g_P[i] = make_float2(z0 * ns, ns);
            g_A[i] = make_float2(0.f, 0.f);
        }
    }
}

// ---------------------------------------------------------------
// K4/K6: float2 scatter propagation via vector RED (4 edges/thread)
// ---------------------------------------------------------------
__global__ void k_prop2(const int* __restrict__ src, const int* __restrict__ dst, int e) {
    int i = (blockIdx.x * blockDim.x + threadIdx.x) * 4;
    if (i + 3 < e) {
        int4 s = *(const int4*)&src[i];
        int4 d = *(const int4*)&dst[i];
        float2 p0 = __ldg(&g_P[s.x]);
        float2 p1 = __ldg(&g_P[s.y]);
        float2 p2 = __ldg(&g_P[s.z]);
        float2 p3 = __ldg(&g_P[s.w]);
        RED2(&g_A[d.x], p0.x, p0.y);
        RED2(&g_A[d.y], p1.x, p1.y);
        RED2(&g_A[d.z], p2.x, p2.y);
        RED2(&g_A[d.w], p3.x, p3.y);
    } else {
        for (; i < e; i++) {
            float2 p = __ldg(&g_P[src[i]]);
            RED2(&g_A[dst[i]], p.x, p.y);
        }
    }
}

// ---------------------------------------------------------------
// K5: rescale after prop1: s1 = A.y*nd; P = (A*nd)*ns; A = 0
// ---------------------------------------------------------------
__global__ void __launch_bounds__(256)
k_rescale1(int n) {
    int i = blockIdx.x * blockDim.x + threadIdx.x;
    if (i >= n) return;
    float2 A = g_A[i];
    float nd = g_ndst[i], ns = g_nsrc[i];
    float u = A.x * nd, ss = A.y * nd;
    g_s1[i] = ss;
    g_P[i] = make_float2(u * ns, ss * ns);
    g_A[i] = make_float2(0.f, 0.f);
}

// ---------------------------------------------------------------
// K7: rescale after prop2: Ps = A.x*nd*ns (s2 read later from A.y)
// ---------------------------------------------------------------
__global__ void __launch_bounds__(256)
k_rescale2(int n) {
    int i = blockIdx.x * blockDim.x + threadIdx.x;
    if (i >= n) return;
    g_Ps[i] = g_A[i].x * g_ndst[i] * g_nsrc[i];
}

// ---------------------------------------------------------------
// K8: final scalar prop: As[dst] += Ps[src], 4 edges/thread
// ---------------------------------------------------------------
__global__ void k_prop1(const int* __restrict__ src, const int* __restrict__ dst, int e) {
    int i = (blockIdx.x * blockDim.x + threadIdx.x) * 4;
    if (i + 3 < e) {
        int4 s = *(const int4*)&src[i];
        int4 d = *(const int4*)&dst[i];
        atomicAdd(&g_As[d.x], __ldg(&g_Ps[s.x]));
        atomicAdd(&g_As[d.y], __ldg(&g_Ps[s.y]));
        atomicAdd(&g_As[d.z], __ldg(&g_Ps[s.z]));
        atomicAdd(&g_As[d.w], __ldg(&g_Ps[s.w]));
    } else {
        for (; i < e; i++)
            atomicAdd(&g_As[dst[i]], __ldg(&g_Ps[src[i]]));
    }
}

// ---------------------------------------------------------------
// K9: per-node combine + pooled output (s2 = A.y*nd inline)
// ---------------------------------------------------------------
__global__ void __launch_bounds__(256)
k_out(const int* __restrict__ gid, float* __restrict__ out, int n) {
    int i = blockIdx.x * blockDim.x + threadIdx.x;
    if (i >= n) return;
    float nd = g_ndst[i];
    float s2 = g_A[i].y * nd;
    float val = g_As[i] * nd + g_c0 * s2 + g_c1 * g_s1[i] + g_c2;
    atomicAdd(&out[gid[i]], val);
}

// ---------------------------------------------------------------
extern "C" void kernel_launch(void* const* d_in, const int* in_sizes, int n_in,
                              void* d_out, int out_size)
{
    const int* feats = (const int*)d_in[0];
    const int* src   = (const int*)d_in[1];
    const int* dst   = (const int*)d_in[2];
    const int* gid   = (const int*)d_in[3];
    int k = 4;
    if (n_in >= 9 && in_sizes[4] == 1) k = 5;
    const float* emb  = (const float*)d_in[k];
    const float* Ws   = (const float*)d_in[k + 1];
    const float* bs   = (const float*)d_in[k + 2];
    const float* wreg = (const float*)d_in[k + 3];
    float* out = (float*)d_out;

    int n = in_sizes[0];
    int e = in_sizes[1];
    int ng = out_size;
    int vocab = in_sizes[k] / HID;

    int nB = (n + 255) / 256;
    int eB = (e / 4 + 256) / 256;   // also covers vocab*16 threads (160k < 400k)

    k_init_fold<<<nB, 256>>>(Ws, bs, wreg, out, n, ng);
    k_deg_tdot<<<eB, 256>>>(src, dst, emb, e, vocab);
    k_p0<<<(n / 4 + 256) / 256, 256>>>(feats, n);

    k_prop2<<<eB, 256>>>(src, dst, e);     // S^1
    k_rescale1<<<nB, 256>>>(n);
    k_prop2<<<eB, 256>>>(src, dst, e);     // S^2
    k_rescale2<<<nB, 256>>>(n);
    k_prop1<<<eB, 256>>>(src, dst, e);     // S^3 (scalar)
    k_out<<<nB, 256>>>(gid, out, n);
}

// round 13
// speedup vs baseline: 1.2677x; 1.0003x over previous
#include <cuda_runtime.h>

#define N_MAX 100000
#define HID 64
#define V_MAX 16384

// ---- persistent scratch (no allocation allowed) ----
__device__ int    g_outdeg[N_MAX];
__device__ int    g_indeg[N_MAX];
__device__ float  g_nsrc[N_MAX];
__device__ float  g_ndst[N_MAX];
__device__ float  g_v[HID];        // W0 W1 W2 wreg
__device__ float  g_c0, g_c1, g_c2;
__device__ float  g_tdot[V_MAX];   // emb_table . v
__device__ float2 g_P[N_MAX];      // prescaled (value, ones) pair
__device__ float2 g_A[N_MAX];      // float2 accumulator
__device__ float  g_Ps[N_MAX];     // prescaled scalar (final prop)
__device__ float  g_As[N_MAX];     // scalar accumulator (100k addrs)
__device__ float  g_s1[N_MAX];     // S^1 1

// vector RED (sm_90+)
#define RED2(addr, a, b) \
    asm volatile("red.global.add.v2.f32 [%0], {%1, %2};" \
                 :: "l"(addr), "f"(a), "f"(b) : "memory")

// ---------------------------------------------------------------
// K1: init + fold. Block 0 folds weights into g_v and bias scalars.
// ---------------------------------------------------------------
__global__ void k_init_fold(const float* __restrict__ Ws, const float* __restrict__ bs,
                            const float* __restrict__ wreg,
                            float* out, int n, int ng) {
    int i = blockIdx.x * blockDim.x + threadIdx.x;
    if (i < n) { g_outdeg[i] = 0; g_indeg[i] = 0; g_As[i] = 0.f; }
    if (i < ng) out[i] = 0.0f;

    if (blockIdx.x == 0) {
        __shared__ float sa[HID], sb[HID];
        int k = threadIdx.x;
        if (k < HID) {
            float s = 0.f;
            #pragma unroll 8
            for (int j = 0; j < HID; j++) s += Ws[2 * HID * HID + k * HID + j] * wreg[j];
            sa[k] = s;
        }
        __syncthreads();
        if (k < HID) {
            float s = 0.f;
            #pragma unroll 8
            for (int j = 0; j < HID; j++) s += Ws[1 * HID * HID + k * HID + j] * sa[j];
            sb[k] = s;
        }
        __syncthreads();
        if (k < HID) {
            float s = 0.f;
            #pragma unroll 8
            for (int j = 0; j < HID; j++) s += Ws[0 * HID * HID + k * HID + j] * sb[j];
            g_v[k] = s;
        }
        if (k == 0) {
            float c2 = 0.f, c1 = 0.f, c0 = 0.f;
            #pragma unroll 8
            for (int j = 0; j < HID; j++) {
                c2 += bs[2 * HID + j] * wreg[j];
                c1 += bs[1 * HID + j] * sa[j];
                c0 += bs[0 * HID + j] * sb[j];
            }
            g_c2 = c2; g_c1 = c1; g_c0 = c0;
        }
    }
}

// ---------------------------------------------------------------
// K2: degree counts (grid-stride, int4 groups, single wave) + tdot
// ---------------------------------------------------------------
__global__ void __launch_bounds__(256)
k_deg_tdot(const int* __restrict__ src, const int* __restrict__ dst,
           const float* __restrict__ emb, int e, int vocab) {
    int nt = gridDim.x * 256;
    int t = blockIdx.x * 256 + threadIdx.x;

    // tdot: 16 lanes per vocab word (fits in one wave: 160k < nt)
    if (t < vocab * 16) {
        int w = t >> 4;
        int l = t & 15;
        float4 ev = __ldg((const float4*)emb + w * 16 + l);
        float4 vv = *(const float4*)&g_v[l * 4];
        float p = ev.x * vv.x + ev.y * vv.y + ev.z * vv.z + ev.w * vv.w;
        p += __shfl_xor_sync(0xffffffffu, p, 8);
        p += __shfl_xor_sync(0xffffffffu, p, 4);
        p += __shfl_xor_sync(0xffffffffu, p, 2);
        p += __shfl_xor_sync(0xffffffffu, p, 1);
        if (l == 0) g_tdot[w] = p;
    }

    int ng4 = e >> 2;
    for (int j = t; j < ng4; j += nt) {
        int4 s = __ldg((const int4*)src + j);
        int4 d = __ldg((const int4*)dst + j);
        atomicAdd(&g_outdeg[s.x], 1); atomicAdd(&g_outdeg[s.y], 1);
        atomicAdd(&g_outdeg[s.z], 1); atomicAdd(&g_outdeg[s.w], 1);
        atomicAdd(&g_indeg[d.x], 1);  atomicAdd(&g_indeg[d.y], 1);
        atomicAdd(&g_indeg[d.z], 1);  atomicAdd(&g_indeg[d.w], 1);
    }
    int base = ng4 << 2;
    int i = base + t;
    if (i < e) {
        atomicAdd(&g_outdeg[src[i]], 1);
        atomicAdd(&g_indeg[dst[i]], 1);
    }
}

// ---------------------------------------------------------------
// K3: norms + P0 = (z0, 1)*nsrc + zero A; 1 node/thread
// ---------------------------------------------------------------
__global__ void __launch_bounds__(256)
k_p0(const int* __restrict__ feats, int n) {
    int i = blockIdx.x * blockDim.x + threadIdx.x;
    if (i >= n) return;
    float ns = rsqrtf(fmaxf((float)g_outdeg[i], 1.0f));
    float nd = rsqrtf(fmaxf((float)g_indeg[i], 1.0f));
    g_nsrc[i] = ns;
    g_ndst[i] = nd;
    float z0 = __ldg(&g_tdot[__ldg(&feats[i])]);
    g_P[i] = make_float2(z0 * ns, ns);
    g_A[i] = make_float2(0.f, 0.f);
}

// ---------------------------------------------------------------
// K4/K6: float2 scatter propagation via vector RED
//        grid-stride int4 groups, single full wave
// ---------------------------------------------------------------
__global__ void __launch_bounds__(256)
k_prop2(const int* __restrict__ src, const int* __restrict__ dst, int e) {
    int nt = gridDim.x * 256;
    int t = blockIdx.x * 256 + threadIdx.x;
    int ng4 = e >> 2;
    for (int j = t; j < ng4; j += nt) {
        int4 s = __ldg((const int4*)src + j);
        int4 d = __ldg((const int4*)dst + j);
        float2 p0 = __ldg(&g_P[s.x]);
        float2 p1 = __ldg(&g_P[s.y]);
        float2 p2 = __ldg(&g_P[s.z]);
        float2 p3 = __ldg(&g_P[s.w]);
        RED2(&g_A[d.x], p0.x, p0.y);
        RED2(&g_A[d.y], p1.x, p1.y);
        RED2(&g_A[d.z], p2.x, p2.y);
        RED2(&g_A[d.w], p3.x, p3.y);
    }
    int i = (ng4 << 2) + t;
    if (i < e) {
        float2 p = __ldg(&g_P[src[i]]);
        RED2(&g_A[dst[i]], p.x, p.y);
    }
}

// ---------------------------------------------------------------
// K5: rescale after prop1: s1 = A.y*nd; P = (A*nd)*ns; A = 0
// ---------------------------------------------------------------
__global__ void __launch_bounds__(256)
k_rescale1(int n) {
    int i = blockIdx.x * blockDim.x + threadIdx.x;
    if (i >= n) return;
    float2 A = g_A[i];
    float nd = g_ndst[i], ns = g_nsrc[i];
    float u = A.x * nd, ss = A.y * nd;
    g_s1[i] = ss;
    g_P[i] = make_float2(u * ns, ss * ns);
    g_A[i] = make_float2(0.f, 0.f);
}

// ---------------------------------------------------------------
// K7: rescale after prop2: Ps = A.x*nd*ns (s2 read later from A.y)
// ---------------------------------------------------------------
__global__ void __launch_bounds__(256)
k_rescale2(int n) {
    int i = blockIdx.x * blockDim.x + threadIdx.x;
    if (i >= n) return;
    g_Ps[i] = g_A[i].x * g_ndst[i] * g_nsrc[i];
}

// ---------------------------------------------------------------
// K8: final scalar prop: As[dst] += Ps[src], grid-stride single wave
// ---------------------------------------------------------------
__global__ void __launch_bounds__(256)
k_prop1(const int* __restrict__ src, const int* __restrict__ dst, int e) {
    int nt = gridDim.x * 256;
    int t = blockIdx.x * 256 + threadIdx.x;
    int ng4 = e >> 2;
    for (int j = t; j < ng4; j += nt) {
        int4 s = __ldg((const int4*)src + j);
        int4 d = __ldg((const int4*)dst + j);
        atomicAdd(&g_As[d.x], __ldg(&g_Ps[s.x]));
        atomicAdd(&g_As[d.y], __ldg(&g_Ps[s.y]));
        atomicAdd(&g_As[d.z], __ldg(&g_Ps[s.z]));
        atomicAdd(&g_As[d.w], __ldg(&g_Ps[s.w]));
    }
    int i = (ng4 << 2) + t;
    if (i < e)
        atomicAdd(&g_As[dst[i]], __ldg(&g_Ps[src[i]]));
}

// ---------------------------------------------------------------
// K9: per-node combine + pooled output (s2 = A.y*nd inline)
// ---------------------------------------------------------------
__global__ void __launch_bounds__(256)
k_out(const int* __restrict__ gid, float* __restrict__ out, int n) {
    int i = blockIdx.x * blockDim.x + threadIdx.x;
    if (i >= n) return;
    float nd = g_ndst[i];
    float s2 = g_A[i].y * nd;
    float val = g_As[i] * nd + g_c0 * s2 + g_c1 * g_s1[i] + g_c2;
    atomicAdd(&out[gid[i]], val);
}

// ---------------------------------------------------------------
extern "C" void kernel_launch(void* const* d_in, const int* in_sizes, int n_in,
                              void* d_out, int out_size)
{
    const int* feats = (const int*)d_in[0];
    const int* src   = (const int*)d_in[1];
    const int* dst   = (const int*)d_in[2];
    const int* gid   = (const int*)d_in[3];
    int k = 4;
    if (n_in >= 9 && in_sizes[4] == 1) k = 5;
    const float* emb  = (const float*)d_in[k];
    const float* Ws   = (const float*)d_in[k + 1];
    const float* bs   = (const float*)d_in[k + 2];
    const float* wreg = (const float*)d_in[k + 3];
    float* out = (float*)d_out;

    int n = in_sizes[0];
    int e = in_sizes[1];
    int ng = out_size;
    int vocab = in_sizes[k] / HID;

    int nB = (n + 255) / 256;

    // one full resident wave for the edge passes (8 blocks/SM at 32 regs)
    int dev = 0, nsm = 148;
    cudaGetDevice(&dev);
    cudaDeviceGetAttribute(&nsm, cudaDevAttrMultiProcessorCount, dev);
    int eB = nsm * 8;
    int maxB = (e / 4 + 255) / 256;     // never more blocks than work groups
    if (eB > maxB) eB = maxB;

    k_init_fold<<<nB, 256>>>(Ws, bs, wreg, out, n, ng);
    k_deg_tdot<<<eB, 256>>>(src, dst, emb, e, vocab);
    k_p0<<<nB, 256>>>(feats, n);

    k_prop2<<<eB, 256>>>(src, dst, e);     // S^1
    k_rescale1<<<nB, 256>>>(n);
    k_prop2<<<eB, 256>>>(src, dst, e);     // S^2
    k_rescale2<<<nB, 256>>>(n);
    k_prop1<<<eB, 256>>>(src, dst, e);     // S^3 (scalar)
    k_out<<<nB, 256>>>(gid, out, n);
}

// round 14
// speedup vs baseline: 1.2711x; 1.0027x over previous
#include <cuda_runtime.h>
#include <cuda_fp16.h>

#define N_MAX 100000
#define HID 64
#define V_MAX 16384

// ---- persistent scratch (no allocation allowed) ----
__device__ int     g_outdeg[N_MAX];
__device__ int     g_indeg[N_MAX];
__device__ float   g_nsrc[N_MAX];
__device__ float   g_ndst[N_MAX];
__device__ float   g_v[HID];        // W0 W1 W2 wreg
__device__ float   g_c0, g_c1, g_c2;
__device__ float   g_tdot[V_MAX];   // emb_table . v
__device__ __half2 g_P[N_MAX];      // prescaled (value, ones) pair — fp16 storage
__device__ float2  g_A[N_MAX];      // fp32 accumulator
__device__ float   g_Ps[N_MAX];     // prescaled scalar (final prop, fp32)
__device__ float   g_As[N_MAX];     // scalar accumulator (100k addrs)
__device__ float   g_s1[N_MAX];     // S^1 1

// vector RED (sm_90+)
#define RED2(addr, a, b) \
    asm volatile("red.global.add.v2.f32 [%0], {%1, %2};" \
                 :: "l"(addr), "f"(a), "f"(b) : "memory")

// ---------------------------------------------------------------
// K1: init + fold. Block 0 folds weights into g_v and bias scalars.
// ---------------------------------------------------------------
__global__ void k_init_fold(const float* __restrict__ Ws, const float* __restrict__ bs,
                            const float* __restrict__ wreg,
                            float* out, int n, int ng) {
    int i = blockIdx.x * blockDim.x + threadIdx.x;
    if (i < n) { g_outdeg[i] = 0; g_indeg[i] = 0; g_As[i] = 0.f; }
    if (i < ng) out[i] = 0.0f;

    if (blockIdx.x == 0) {
        __shared__ float sa[HID], sb[HID];
        int k = threadIdx.x;
        if (k < HID) {
            float s = 0.f;
            #pragma unroll 8
            for (int j = 0; j < HID; j++) s += Ws[2 * HID * HID + k * HID + j] * wreg[j];
            sa[k] = s;
        }
        __syncthreads();
        if (k < HID) {
            float s = 0.f;
            #pragma unroll 8
            for (int j = 0; j < HID; j++) s += Ws[1 * HID * HID + k * HID + j] * sa[j];
            sb[k] = s;
        }
        __syncthreads();
        if (k < HID) {
            float s = 0.f;
            #pragma unroll 8
            for (int j = 0; j < HID; j++) s += Ws[0 * HID * HID + k * HID + j] * sb[j];
            g_v[k] = s;
        }
        if (k == 0) {
            float c2 = 0.f, c1 = 0.f, c0 = 0.f;
            #pragma unroll 8
            for (int j = 0; j < HID; j++) {
                c2 += bs[2 * HID + j] * wreg[j];
                c1 += bs[1 * HID + j] * sa[j];
                c0 += bs[0 * HID + j] * sb[j];
            }
            g_c2 = c2; g_c1 = c1; g_c0 = c0;
        }
    }
}

// ---------------------------------------------------------------
// K2: degree counts (grid-stride, int4 groups, single wave) + tdot
// ---------------------------------------------------------------
__global__ void __launch_bounds__(256)
k_deg_tdot(const int* __restrict__ src, const int* __restrict__ dst,
           const float* __restrict__ emb, int e, int vocab) {
    int nt = gridDim.x * 256;
    int t = blockIdx.x * 256 + threadIdx.x;

    if (t < vocab * 16) {
        int w = t >> 4;
        int l = t & 15;
        float4 ev = __ldg((const float4*)emb + w * 16 + l);
        float4 vv = *(const float4*)&g_v[l * 4];
        float p = ev.x * vv.x + ev.y * vv.y + ev.z * vv.z + ev.w * vv.w;
        p += __shfl_xor_sync(0xffffffffu, p, 8);
        p += __shfl_xor_sync(0xffffffffu, p, 4);
        p += __shfl_xor_sync(0xffffffffu, p, 2);
        p += __shfl_xor_sync(0xffffffffu, p, 1);
        if (l == 0) g_tdot[w] = p;
    }

    int ng4 = e >> 2;
    for (int j = t; j < ng4; j += nt) {
        int4 s = __ldg((const int4*)src + j);
        int4 d = __ldg((const int4*)dst + j);
        atomicAdd(&g_outdeg[s.x], 1); atomicAdd(&g_outdeg[s.y], 1);
        atomicAdd(&g_outdeg[s.z], 1); atomicAdd(&g_outdeg[s.w], 1);
        atomicAdd(&g_indeg[d.x], 1);  atomicAdd(&g_indeg[d.y], 1);
        atomicAdd(&g_indeg[d.z], 1);  atomicAdd(&g_indeg[d.w], 1);
    }
    int i = (ng4 << 2) + t;
    if (i < e) {
        atomicAdd(&g_outdeg[src[i]], 1);
        atomicAdd(&g_indeg[dst[i]], 1);
    }
}

// ---------------------------------------------------------------
// K3: norms + P0 = half2(z0*ns, ns) + zero A
// ---------------------------------------------------------------
__global__ void __launch_bounds__(256)
k_p0(const int* __restrict__ feats, int n) {
    int i = blockIdx.x * blockDim.x + threadIdx.x;
    if (i >= n) return;
    float ns = rsqrtf(fmaxf((float)g_outdeg[i], 1.0f));
    float nd = rsqrtf(fmaxf((float)g_indeg[i], 1.0f));
    g_nsrc[i] = ns;
    g_ndst[i] = nd;
    float z0 = __ldg(&g_tdot[__ldg(&feats[i])]);
    g_P[i] = __floats2half2_rn(z0 * ns, ns);
    g_A[i] = make_float2(0.f, 0.f);
}

// ---------------------------------------------------------------
// K4/K6: prop via fp16 gather + fp32 vector RED, single full wave
// ---------------------------------------------------------------
__global__ void __launch_bounds__(256)
k_prop2(const int* __restrict__ src, const int* __restrict__ dst, int e) {
    int nt = gridDim.x * 256;
    int t = blockIdx.x * 256 + threadIdx.x;
    int ng4 = e >> 2;
    for (int j = t; j < ng4; j += nt) {
        int4 s = __ldg((const int4*)src + j);
        int4 d = __ldg((const int4*)dst + j);
        __half2 h0 = __ldg(&g_P[s.x]);
        __half2 h1 = __ldg(&g_P[s.y]);
        __half2 h2 = __ldg(&g_P[s.z]);
        __half2 h3 = __ldg(&g_P[s.w]);
        float2 p0 = __half22float2(h0);
        float2 p1 = __half22float2(h1);
        float2 p2 = __half22float2(h2);
        float2 p3 = __half22float2(h3);
        RED2(&g_A[d.x], p0.x, p0.y);
        RED2(&g_A[d.y], p1.x, p1.y);
        RED2(&g_A[d.z], p2.x, p2.y);
        RED2(&g_A[d.w], p3.x, p3.y);
    }
    int i = (ng4 << 2) + t;
    if (i < e) {
        float2 p = __half22float2(__ldg(&g_P[src[i]]));
        RED2(&g_A[dst[i]], p.x, p.y);
    }
}

// ---------------------------------------------------------------
// K5: rescale after prop1: s1 = A.y*nd; P = half2((A*nd)*ns); A = 0
// ---------------------------------------------------------------
__global__ void __launch_bounds__(256)
k_rescale1(int n) {
    int i = blockIdx.x * blockDim.x + threadIdx.x;
    if (i >= n) return;
    float2 A = g_A[i];
    float nd = g_ndst[i], ns = g_nsrc[i];
    float u = A.x * nd, ss = A.y * nd;
    g_s1[i] = ss;
    g_P[i] = __floats2half2_rn(u * ns, ss * ns);
    g_A[i] = make_float2(0.f, 0.f);
}

// ---------------------------------------------------------------
// K7: rescale after prop2: Ps = A.x*nd*ns (fp32; s2 read later from A.y)
// ---------------------------------------------------------------
__global__ void __launch_bounds__(256)
k_rescale2(int n) {
    int i = blockIdx.x * blockDim.x + threadIdx.x;
    if (i >= n) return;
    g_Ps[i] = g_A[i].x * g_ndst[i] * g_nsrc[i];
}

// ---------------------------------------------------------------
// K8: final scalar prop (fp32): As[dst] += Ps[src], single wave
// ---------------------------------------------------------------
__global__ void __launch_bounds__(256)
k_prop1(const int* __restrict__ src, const int* __restrict__ dst, int e) {
    int nt = gridDim.x * 256;
    int t = blockIdx.x * 256 + threadIdx.x;
    int ng4 = e >> 2;
    for (int j = t; j < ng4; j += nt) {
        int4 s = __ldg((const int4*)src + j);
        int4 d = __ldg((const int4*)dst + j);
        atomicAdd(&g_As[d.x], __ldg(&g_Ps[s.x]));
        atomicAdd(&g_As[d.y], __ldg(&g_Ps[s.y]));
        atomicAdd(&g_As[d.z], __ldg(&g_Ps[s.z]));
        atomicAdd(&g_As[d.w], __ldg(&g_Ps[s.w]));
    }
    int i = (ng4 << 2) + t;
    if (i < e)
        atomicAdd(&g_As[dst[i]], __ldg(&g_Ps[src[i]]));
}

// ---------------------------------------------------------------
// K9: per-node combine + pooled output (s2 = A.y*nd inline)
// ---------------------------------------------------------------
__global__ void __launch_bounds__(256)
k_out(const int* __restrict__ gid, float* __restrict__ out, int n) {
    int i = blockIdx.x * blockDim.x + threadIdx.x;
    if (i >= n) return;
    float nd = g_ndst[i];
    float s2 = g_A[i].y * nd;
    float val = g_As[i] * nd + g_c0 * s2 + g_c1 * g_s1[i] + g_c2;
    atomicAdd(&out[gid[i]], val);
}

// ---------------------------------------------------------------
extern "C" void kernel_launch(void* const* d_in, const int* in_sizes, int n_in,
                              void* d_out, int out_size)
{
    const int* feats = (const int*)d_in[0];
    const int* src   = (const int*)d_in[1];
    const int* dst   = (const int*)d_in[2];
    const int* gid   = (const int*)d_in[3];
    int k = 4;
    if (n_in >= 9 && in_sizes[4] == 1) k = 5;
    const float* emb  = (const float*)d_in[k];
    const float* Ws   = (const float*)d_in[k + 1];
    const float* bs   = (const float*)d_in[k + 2];
    const float* wreg = (const float*)d_in[k + 3];
    float* out = (float*)d_out;

    int n = in_sizes[0];
    int e = in_sizes[1];
    int ng = out_size;
    int vocab = in_sizes[k] / HID;

    int nB = (n + 255) / 256;

    int dev = 0, nsm = 148;
    cudaGetDevice(&dev);
    cudaDeviceGetAttribute(&nsm, cudaDevAttrMultiProcessorCount, dev);
    int eB = nsm * 8;
    int maxB = (e / 4 + 255) / 256;
    if (eB > maxB) eB = maxB;

    k_init_fold<<<nB, 256>>>(Ws, bs, wreg, out, n, ng);
    k_deg_tdot<<<eB, 256>>>(src, dst, emb, e, vocab);
    k_p0<<<nB, 256>>>(feats, n);

    k_prop2<<<eB, 256>>>(src, dst, e);     // S^1
    k_rescale1<<<nB, 256>>>(n);
    k_prop2<<<eB, 256>>>(src, dst, e);     // S^2
    k_rescale2<<<nB, 256>>>(n);
    k_prop1<<<eB, 256>>>(src, dst, e);     // S^3 (scalar)
    k_out<<<nB, 256>>>(gid, out, n);
}

// round 15
// speedup vs baseline: 1.4104x; 1.1096x over previous
#include <cuda_runtime.h>
#include <cuda_fp16.h>

#define N_MAX 100000
#define HID 64
#define V_MAX 16384

// ---- persistent scratch (no allocation allowed) ----
__device__ int     g_outdeg[N_MAX];
__device__ float   g_nsrc[N_MAX];
__device__ float   g_ndst[N_MAX];
__device__ float   g_v[HID];        // W0 W1 W2 wreg
__device__ float   g_c0, g_c1, g_c2;
__device__ float   g_tdot[V_MAX];   // emb_table . v
__device__ __half2 g_P[N_MAX];      // prescaled (value, ones) pair — fp16
__device__ float4  g_A4[N_MAX];     // fp32 accumulator (x=val, y=ones, z=indeg)
__device__ float   g_Ps[N_MAX];     // prescaled scalar (final prop, fp32)
__device__ float   g_As[N_MAX];     // scalar accumulator (100k addrs)
__device__ float   g_s1[N_MAX];     // S^1 1

// vector REDs (sm_90+)
#define RED2(addr, a, b) \
    asm volatile("red.global.add.v2.f32 [%0], {%1, %2};" \
                 :: "l"(addr), "f"(a), "f"(b) : "memory")
#define RED4(addr, a, b, c, d) \
    asm volatile("red.global.add.v4.f32 [%0], {%1, %2, %3, %4};" \
                 :: "l"(addr), "f"(a), "f"(b), "f"(c), "f"(d) : "memory")

// ---------------------------------------------------------------
// K1: init + fold. Block 0 folds weights into g_v and bias scalars.
// ---------------------------------------------------------------
__global__ void k_init_fold(const float* __restrict__ Ws, const float* __restrict__ bs,
                            const float* __restrict__ wreg,
                            float* out, int n, int ng) {
    int i = blockIdx.x * blockDim.x + threadIdx.x;
    if (i < n) {
        g_outdeg[i] = 0;
        g_As[i] = 0.f;
        g_A4[i] = make_float4(0.f, 0.f, 0.f, 0.f);
    }
    if (i < ng) out[i] = 0.0f;

    if (blockIdx.x == 0) {
        __shared__ float sa[HID], sb[HID];
        int k = threadIdx.x;
        if (k < HID) {
            float s = 0.f;
            #pragma unroll 8
            for (int j = 0; j < HID; j++) s += Ws[2 * HID * HID + k * HID + j] * wreg[j];
            sa[k] = s;
        }
        __syncthreads();
        if (k < HID) {
            float s = 0.f;
            #pragma unroll 8
            for (int j = 0; j < HID; j++) s += Ws[1 * HID * HID + k * HID + j] * sa[j];
            sb[k] = s;
        }
        __syncthreads();
        if (k < HID) {
            float s = 0.f;
            #pragma unroll 8
            for (int j = 0; j < HID; j++) s += Ws[0 * HID * HID + k * HID + j] * sb[j];
            g_v[k] = s;
        }
        if (k == 0) {
            float c2 = 0.f, c1 = 0.f, c0 = 0.f;
            #pragma unroll 8
            for (int j = 0; j < HID; j++) {
                c2 += bs[2 * HID + j] * wreg[j];
                c1 += bs[1 * HID + j] * sa[j];
                c0 += bs[0 * HID + j] * sb[j];
            }
            g_c2 = c2; g_c1 = c1; g_c0 = c0;
        }
    }
}

// ---------------------------------------------------------------
// K2: OUT-degree only (1 RED/edge — indeg comes free from S^1) + tdot
// ---------------------------------------------------------------
__global__ void __launch_bounds__(256)
k_deg_tdot(const int* __restrict__ src, const float* __restrict__ emb,
           int e, int vocab) {
    int nt = gridDim.x * 256;
    int t = blockIdx.x * 256 + threadIdx.x;

    if (t < vocab * 16) {
        int w = t >> 4;
        int l = t & 15;
        float4 ev = __ldg((const float4*)emb + w * 16 + l);
        float4 vv = *(const float4*)&g_v[l * 4];
        float p = ev.x * vv.x + ev.y * vv.y + ev.z * vv.z + ev.w * vv.w;
        p += __shfl_xor_sync(0xffffffffu, p, 8);
        p += __shfl_xor_sync(0xffffffffu, p, 4);
        p += __shfl_xor_sync(0xffffffffu, p, 2);
        p += __shfl_xor_sync(0xffffffffu, p, 1);
        if (l == 0) g_tdot[w] = p;
    }

    int ng4 = e >> 2;
    for (int j = t; j < ng4; j += nt) {
        int4 s = __ldcs((const int4*)src + j);
        atomicAdd(&g_outdeg[s.x], 1); atomicAdd(&g_outdeg[s.y], 1);
        atomicAdd(&g_outdeg[s.z], 1); atomicAdd(&g_outdeg[s.w], 1);
    }
    int i = (ng4 << 2) + t;
    if (i < e)
        atomicAdd(&g_outdeg[src[i]], 1);
}

// ---------------------------------------------------------------
// K3: ns + P0 = half2(z0*ns, ns)   (nd derived later from A4.z)
// ---------------------------------------------------------------
__global__ void __launch_bounds__(256)
k_p0(const int* __restrict__ feats, int n) {
    int i = blockIdx.x * blockDim.x + threadIdx.x;
    if (i >= n) return;
    float ns = rsqrtf(fmaxf((float)g_outdeg[i], 1.0f));
    g_nsrc[i] = ns;
    float z0 = __ldg(&g_tdot[__ldg(&feats[i])]);
    g_P[i] = __floats2half2_rn(z0 * ns, ns);
}

// ---------------------------------------------------------------
// K4: prop S^1 — v4 RED carries {val, ones, 1(indeg), 0}
// ---------------------------------------------------------------
__global__ void __launch_bounds__(256)
k_prop_a(const int* __restrict__ src, const int* __restrict__ dst, int e) {
    int nt = gridDim.x * 256;
    int t = blockIdx.x * 256 + threadIdx.x;
    int ng4 = e >> 2;
    for (int j = t; j < ng4; j += nt) {
        int4 s = __ldcs((const int4*)src + j);
        int4 d = __ldcs((const int4*)dst + j);
        float2 p0 = __half22float2(__ldg(&g_P[s.x]));
        float2 p1 = __half22float2(__ldg(&g_P[s.y]));
        float2 p2 = __half22float2(__ldg(&g_P[s.z]));
        float2 p3 = __half22float2(__ldg(&g_P[s.w]));
        RED4(&g_A4[d.x], p0.x, p0.y, 1.0f, 0.0f);
        RED4(&g_A4[d.y], p1.x, p1.y, 1.0f, 0.0f);
        RED4(&g_A4[d.z], p2.x, p2.y, 1.0f, 0.0f);
        RED4(&g_A4[d.w], p3.x, p3.y, 1.0f, 0.0f);
    }
    int i = (ng4 << 2) + t;
    if (i < e) {
        float2 p = __half22float2(__ldg(&g_P[src[i]]));
        RED4(&g_A4[dst[i]], p.x, p.y, 1.0f, 0.0f);
    }
}

// ---------------------------------------------------------------
// K5: rescale1: nd = rsqrt(max(indeg,1)); s1 = A.y*nd;
//     P = half2((A.x*nd)*ns, s1*ns); zero A.x/.y
// ---------------------------------------------------------------
__global__ void __launch_bounds__(256)
k_rescale1(int n) {
    int i = blockIdx.x * blockDim.x + threadIdx.x;
    if (i >= n) return;
    float4 A = g_A4[i];
    float nd = rsqrtf(fmaxf(A.z, 1.0f));
    float ns = g_nsrc[i];
    g_ndst[i] = nd;
    float u = A.x * nd, ss = A.y * nd;
    g_s1[i] = ss;
    g_P[i] = __floats2half2_rn(u * ns, ss * ns);
    *(float2*)&g_A4[i] = make_float2(0.f, 0.f);
}

// ---------------------------------------------------------------
// K6: prop S^2 — v2 RED into A4.x/.y
// ---------------------------------------------------------------
__global__ void __launch_bounds__(256)
k_prop_b(const int* __restrict__ src, const int* __restrict__ dst, int e) {
    int nt = gridDim.x * 256;
    int t = blockIdx.x * 256 + threadIdx.x;
    int ng4 = e >> 2;
    for (int j = t; j < ng4; j += nt) {
        int4 s = __ldcs((const int4*)src + j);
        int4 d = __ldcs((const int4*)dst + j);
        float2 p0 = __half22float2(__ldg(&g_P[s.x]));
        float2 p1 = __half22float2(__ldg(&g_P[s.y]));
        float2 p2 = __half22float2(__ldg(&g_P[s.z]));
        float2 p3 = __half22float2(__ldg(&g_P[s.w]));
        RED2((float*)&g_A4[d.x], p0.x, p0.y);
        RED2((float*)&g_A4[d.y], p1.x, p1.y);
        RED2((float*)&g_A4[d.z], p2.x, p2.y);
        RED2((float*)&g_A4[d.w], p3.x, p3.y);
    }
    int i = (ng4 << 2) + t;
    if (i < e) {
        float2 p = __half22float2(__ldg(&g_P[src[i]]));
        RED2((float*)&g_A4[dst[i]], p.x, p.y);
    }
}

// ---------------------------------------------------------------
// K7: rescale2: Ps = A.x*nd*ns (s2 read later from A.y)
// ---------------------------------------------------------------
__global__ void __launch_bounds__(256)
k_rescale2(int n) {
    int i = blockIdx.x * blockDim.x + threadIdx.x;
    if (i >= n) return;
    g_Ps[i] = g_A4[i].x * g_ndst[i] * g_nsrc[i];
}

// ---------------------------------------------------------------
// K8: final scalar prop: As[dst] += Ps[src]
// ---------------------------------------------------------------
__global__ void __launch_bounds__(256)
k_prop1(const int* __restrict__ src, const int* __restrict__ dst, int e) {
    int nt = gridDim.x * 256;
    int t = blockIdx.x * 256 + threadIdx.x;
    int ng4 = e >> 2;
    for (int j = t; j < ng4; j += nt) {
        int4 s = __ldcs((const int4*)src + j);
        int4 d = __ldcs((const int4*)dst + j);
        atomicAdd(&g_As[d.x], __ldg(&g_Ps[s.x]));
        atomicAdd(&g_As[d.y], __ldg(&g_Ps[s.y]));
        atomicAdd(&g_As[d.z], __ldg(&g_Ps[s.z]));
        atomicAdd(&g_As[d.w], __ldg(&g_Ps[s.w]));
    }
    int i = (ng4 << 2) + t;
    if (i < e)
        atomicAdd(&g_As[dst[i]], __ldg(&g_Ps[src[i]]));
}

// ---------------------------------------------------------------
// K9: per-node combine + pooled output (s2 = A.y*nd inline)
// ---------------------------------------------------------------
__global__ void __launch_bounds__(256)
k_out(const int* __restrict__ gid, float* __restrict__ out, int n) {
    int i = blockIdx.x * blockDim.x + threadIdx.x;
    if (i >= n) return;
    float nd = g_ndst[i];
    float s2 = g_A4[i].y * nd;
    float val = g_As[i] * nd + g_c0 * s2 + g_c1 * g_s1[i] + g_c2;
    atomicAdd(&out[gid[i]], val);
}

// ---------------------------------------------------------------
extern "C" void kernel_launch(void* const* d_in, const int* in_sizes, int n_in,
                              void* d_out, int out_size)
{
    const int* feats = (const int*)d_in[0];
    const int* src   = (const int*)d_in[1];
    const int* dst   = (const int*)d_in[2];
    const int* gid   = (const int*)d_in[3];
    int k = 4;
    if (n_in >= 9 && in_sizes[4] == 1) k = 5;
    const float* emb  = (const float*)d_in[k];
    const float* Ws   = (const float*)d_in[k + 1];
    const float* bs   = (const float*)d_in[k + 2];
    const float* wreg = (const float*)d_in[k + 3];
    float* out = (float*)d_out;

    int n = in_sizes[0];
    int e = in_sizes[1];
    int ng = out_size;
    int vocab = in_sizes[k] / HID;

    int nB = (n + 255) / 256;

    int dev = 0, nsm = 148;
    cudaGetDevice(&dev);
    cudaDeviceGetAttribute(&nsm, cudaDevAttrMultiProcessorCount, dev);
    int eB = nsm * 8;
    int maxB = (e / 4 + 255) / 256;
    if (eB > maxB) eB = maxB;

    k_init_fold<<<nB, 256>>>(Ws, bs, wreg, out, n, ng);
    k_deg_tdot<<<eB, 256>>>(src, emb, e, vocab);
    k_p0<<<nB, 256>>>(feats, n);

    k_prop_a<<<eB, 256>>>(src, dst, e);    // S^1 (+indeg)
    k_rescale1<<<nB, 256>>>(n);
    k_prop_b<<<eB, 256>>>(src, dst, e);    // S^2
    k_rescale2<<<nB, 256>>>(n);
    k_prop1<<<eB, 256>>>(src, dst, e);     // S^3 (scalar)
    k_out<<<nB, 256>>>(gid, out, n);
}

// round 16
// speedup vs baseline: 1.4317x; 1.0152x over previous
#include <cuda_runtime.h>
#include <cuda_fp16.h>

#define N_MAX 100000
#define HID 64
#define V_MAX 16384

// ---- persistent scratch (no allocation allowed) ----
__device__ int     g_outdeg[N_MAX];
__device__ float   g_nsrc[N_MAX];
__device__ float   g_ndst[N_MAX];
__device__ float   g_v[HID];        // W0 W1 W2 wreg
__device__ float   g_c0, g_c1, g_c2;
__device__ float   g_tdot[V_MAX];   // emb_table . v
__device__ __half2 g_P[N_MAX];      // prescaled (value, ones) pair — fp16
__device__ float4  g_A4[N_MAX];     // fp32 accumulator (x=val, y=ones, z=indeg)
__device__ float   g_Ps[N_MAX];     // prescaled scalar (final prop, fp32)
__device__ float   g_As[N_MAX];     // scalar accumulator (100k addrs)
__device__ float   g_s1[N_MAX];     // S^1 1

// vector REDs (sm_90+)
#define RED2(addr, a, b) \
    asm volatile("red.global.add.v2.f32 [%0], {%1, %2};" \
                 :: "l"(addr), "f"(a), "f"(b) : "memory")
#define RED4(addr, a, b, c, d) \
    asm volatile("red.global.add.v4.f32 [%0], {%1, %2, %3, %4};" \
                 :: "l"(addr), "f"(a), "f"(b), "f"(c), "f"(d) : "memory")

// ---------------------------------------------------------------
// K1: init + fold. Block 0 folds weights into g_v and bias scalars.
// ---------------------------------------------------------------
__global__ void k_init_fold(const float* __restrict__ Ws, const float* __restrict__ bs,
                            const float* __restrict__ wreg,
                            float* out, int n, int ng) {
    int i = blockIdx.x * blockDim.x + threadIdx.x;
    if (i < n) {
        g_outdeg[i] = 0;
        g_As[i] = 0.f;
        g_A4[i] = make_float4(0.f, 0.f, 0.f, 0.f);
    }
    if (i < ng) out[i] = 0.0f;

    if (blockIdx.x == 0) {
        __shared__ float sa[HID], sb[HID];
        int k = threadIdx.x;
        if (k < HID) {
            float s = 0.f;
            #pragma unroll 8
            for (int j = 0; j < HID; j++) s += Ws[2 * HID * HID + k * HID + j] * wreg[j];
            sa[k] = s;
        }
        __syncthreads();
        if (k < HID) {
            float s = 0.f;
            #pragma unroll 8
            for (int j = 0; j < HID; j++) s += Ws[1 * HID * HID + k * HID + j] * sa[j];
            sb[k] = s;
        }
        __syncthreads();
        if (k < HID) {
            float s = 0.f;
            #pragma unroll 8
            for (int j = 0; j < HID; j++) s += Ws[0 * HID * HID + k * HID + j] * sb[j];
            g_v[k] = s;
        }
        if (k == 0) {
            float c2 = 0.f, c1 = 0.f, c0 = 0.f;
            #pragma unroll 8
            for (int j = 0; j < HID; j++) {
                c2 += bs[2 * HID + j] * wreg[j];
                c1 += bs[1 * HID + j] * sa[j];
                c0 += bs[0 * HID + j] * sb[j];
            }
            g_c2 = c2; g_c1 = c1; g_c0 = c0;
        }
    }
}

// ---------------------------------------------------------------
// K2: OUT-degree only + tdot
// ---------------------------------------------------------------
__global__ void __launch_bounds__(256)
k_deg_tdot(const int* __restrict__ src, const float* __restrict__ emb,
           int e, int vocab) {
    cudaGridDependencySynchronize();
    int nt = gridDim.x * 256;
    int t = blockIdx.x * 256 + threadIdx.x;

    if (t < vocab * 16) {
        int w = t >> 4;
        int l = t & 15;
        float4 ev = __ldg((const float4*)emb + w * 16 + l);
        float4 vv = *(const float4*)&g_v[l * 4];
        float p = ev.x * vv.x + ev.y * vv.y + ev.z * vv.z + ev.w * vv.w;
        p += __shfl_xor_sync(0xffffffffu, p, 8);
        p += __shfl_xor_sync(0xffffffffu, p, 4);
        p += __shfl_xor_sync(0xffffffffu, p, 2);
        p += __shfl_xor_sync(0xffffffffu, p, 1);
        if (l == 0) g_tdot[w] = p;
    }

    int ng4 = e >> 2;
    for (int j = t; j < ng4; j += nt) {
        int4 s = __ldcs((const int4*)src + j);
        atomicAdd(&g_outdeg[s.x], 1); atomicAdd(&g_outdeg[s.y], 1);
        atomicAdd(&g_outdeg[s.z], 1); atomicAdd(&g_outdeg[s.w], 1);
    }
    int i = (ng4 << 2) + t;
    if (i < e)
        atomicAdd(&g_outdeg[src[i]], 1);
}

// ---------------------------------------------------------------
// K3: ns + P0 = half2(z0*ns, ns)
// ---------------------------------------------------------------
__global__ void __launch_bounds__(256)
k_p0(const int* __restrict__ feats, int n) {
    cudaGridDependencySynchronize();
    int i = blockIdx.x * blockDim.x + threadIdx.x;
    if (i >= n) return;
    float ns = rsqrtf(fmaxf((float)g_outdeg[i], 1.0f));
    g_nsrc[i] = ns;
    float z0 = __ldg(&g_tdot[__ldg(&feats[i])]);
    g_P[i] = __floats2half2_rn(z0 * ns, ns);
}

// ---------------------------------------------------------------
// K4: prop S^1 — v4 RED carries {val, ones, 1(indeg), 0}
// ---------------------------------------------------------------
__global__ void __launch_bounds__(256)
k_prop_a(const int* __restrict__ src, const int* __restrict__ dst, int e) {
    cudaGridDependencySynchronize();
    int nt = gridDim.x * 256;
    int t = blockIdx.x * 256 + threadIdx.x;
    int ng4 = e >> 2;
    for (int j = t; j < ng4; j += nt) {
        int4 s = __ldcs((const int4*)src + j);
        int4 d = __ldcs((const int4*)dst + j);
        float2 p0 = __half22float2(__ldg(&g_P[s.x]));
        float2 p1 = __half22float2(__ldg(&g_P[s.y]));
        float2 p2 = __half22float2(__ldg(&g_P[s.z]));
        float2 p3 = __half22float2(__ldg(&g_P[s.w]));
        RED4(&g_A4[d.x], p0.x, p0.y, 1.0f, 0.0f);
        RED4(&g_A4[d.y], p1.x, p1.y, 1.0f, 0.0f);
        RED4(&g_A4[d.z], p2.x, p2.y, 1.0f, 0.0f);
        RED4(&g_A4[d.w], p3.x, p3.y, 1.0f, 0.0f);
    }
    int i = (ng4 << 2) + t;
    if (i < e) {
        float2 p = __half22float2(__ldg(&g_P[src[i]]));
        RED4(&g_A4[dst[i]], p.x, p.y, 1.0f, 0.0f);
    }
}

// ---------------------------------------------------------------
// K5: rescale1: nd = rsqrt(max(indeg,1)); s1 = A.y*nd;
//     P = half2((A.x*nd)*ns, s1*ns); zero A.x/.y
// ---------------------------------------------------------------
__global__ void __launch_bounds__(256)
k_rescale1(int n) {
    cudaGridDependencySynchronize();
    int i = blockIdx.x * blockDim.x + threadIdx.x;
    if (i >= n) return;
    float4 A = g_A4[i];
    float nd = rsqrtf(fmaxf(A.z, 1.0f));
    float ns = g_nsrc[i];
    g_ndst[i] = nd;
    float u = A.x * nd, ss = A.y * nd;
    g_s1[i] = ss;
    g_P[i] = __floats2half2_rn(u * ns, ss * ns);
    *(float2*)&g_A4[i] = make_float2(0.f, 0.f);
}

// ---------------------------------------------------------------
// K6: prop S^2 — v2 RED into A4.x/.y
// ---------------------------------------------------------------
__global__ void __launch_bounds__(256)
k_prop_b(const int* __restrict__ src, const int* __restrict__ dst, int e) {
    cudaGridDependencySynchronize();
    int nt = gridDim.x * 256;
    int t = blockIdx.x * 256 + threadIdx.x;
    int ng4 = e >> 2;
    for (int j = t; j < ng4; j += nt) {
        int4 s = __ldcs((const int4*)src + j);
        int4 d = __ldcs((const int4*)dst + j);
        float2 p0 = __half22float2(__ldg(&g_P[s.x]));
        float2 p1 = __half22float2(__ldg(&g_P[s.y]));
        float2 p2 = __half22float2(__ldg(&g_P[s.z]));
        float2 p3 = __half22float2(__ldg(&g_P[s.w]));
        RED2((float*)&g_A4[d.x], p0.x, p0.y);
        RED2((float*)&g_A4[d.y], p1.x, p1.y);
        RED2((float*)&g_A4[d.z], p2.x, p2.y);
        RED2((float*)&g_A4[d.w], p3.x, p3.y);
    }
    int i = (ng4 << 2) + t;
    if (i < e) {
        float2 p = __half22float2(__ldg(&g_P[src[i]]));
        RED2((float*)&g_A4[dst[i]], p.x, p.y);
    }
}

// ---------------------------------------------------------------
// K7: rescale2: Ps = A.x*nd*ns
// ---------------------------------------------------------------
__global__ void __launch_bounds__(256)
k_rescale2(int n) {
    cudaGridDependencySynchronize();
    int i = blockIdx.x * blockDim.x + threadIdx.x;
    if (i >= n) return;
    g_Ps[i] = g_A4[i].x * g_ndst[i] * g_nsrc[i];
}

// ---------------------------------------------------------------
// K8: final scalar prop: As[dst] += Ps[src]
// ---------------------------------------------------------------
__global__ void __launch_bounds__(256)
k_prop1(const int* __restrict__ src, const int* __restrict__ dst, int e) {
    cudaGridDependencySynchronize();
    int nt = gridDim.x * 256;
    int t = blockIdx.x * 256 + threadIdx.x;
    int ng4 = e >> 2;
    for (int j = t; j < ng4; j += nt) {
        int4 s = __ldcs((const int4*)src + j);
        int4 d = __ldcs((const int4*)dst + j);
        atomicAdd(&g_As[d.x], __ldg(&g_Ps[s.x]));
        atomicAdd(&g_As[d.y], __ldg(&g_Ps[s.y]));
        atomicAdd(&g_As[d.z], __ldg(&g_Ps[s.z]));
        atomicAdd(&g_As[d.w], __ldg(&g_Ps[s.w]));
    }
    int i = (ng4 << 2) + t;
    if (i < e)
        atomicAdd(&g_As[dst[i]], __ldg(&g_Ps[src[i]]));
}

// ---------------------------------------------------------------
// K9: per-node combine + pooled output
// ---------------------------------------------------------------
__global__ void __launch_bounds__(256)
k_out(const int* __restrict__ gid, float* __restrict__ out, int n) {
    cudaGridDependencySynchronize();
    int i = blockIdx.x * blockDim.x + threadIdx.x;
    if (i >= n) return;
    float nd = g_ndst[i];
    float s2 = g_A4[i].y * nd;
    float val = g_As[i] * nd + g_c0 * s2 + g_c1 * g_s1[i] + g_c2;
    atomicAdd(&out[gid[i]], val);
}

// ---------------------------------------------------------------
// PDL launch helper (programmatic stream serialization)
// ---------------------------------------------------------------
template <typename F, typename... Args>
static inline void launch_pdl(F kern, int grid, bool pdl, Args... args) {
    cudaLaunchConfig_t cfg = {};
    cfg.gridDim = dim3(grid, 1, 1);
    cfg.blockDim = dim3(256, 1, 1);
    cfg.dynamicSmemBytes = 0;
    cfg.stream = 0;
    cudaLaunchAttribute attr[1];
    attr[0].id = cudaLaunchAttributeProgrammaticStreamSerialization;
    attr[0].val.programmaticStreamSerializationAllowed = 1;
    cfg.attrs = attr;
    cfg.numAttrs = pdl ? 1 : 0;
    cudaLaunchKernelEx(&cfg, kern, args...);
}

// ---------------------------------------------------------------
extern "C" void kernel_launch(void* const* d_in, const int* in_sizes, int n_in,
                              void* d_out, int out_size)
{
    const int* feats = (const int*)d_in[0];
    const int* src   = (const int*)d_in[1];
    const int* dst   = (const int*)d_in[2];
    const int* gid   = (const int*)d_in[3];
    int k = 4;
    if (n_in >= 9 && in_sizes[4] == 1) k = 5;
    const float* emb  = (const float*)d_in[k];
    const float* Ws   = (const float*)d_in[k + 1];
    const float* bs   = (const float*)d_in[k + 2];
    const float* wreg = (const float*)d_in[k + 3];
    float* out = (float*)d_out;

    int n = in_sizes[0];
    int e = in_sizes[1];
    int ng = out_size;
    int vocab = in_sizes[k] / HID;

    int nB = (n + 255) / 256;

    int dev = 0, nsm = 148;
    cudaGetDevice(&dev);
    cudaDeviceGetAttribute(&nsm, cudaDevAttrMultiProcessorCount, dev);
    int eB = nsm * 8;
    int maxB = (e / 4 + 255) / 256;
    if (eB > maxB) eB = maxB;

    launch_pdl(k_init_fold, nB, false, Ws, bs, wreg, out, n, ng);
    launch_pdl(k_deg_tdot, eB, true, src, emb, e, vocab);
    launch_pdl(k_p0, nB, true, feats, n);
    launch_pdl(k_prop_a, eB, true, src, dst, e);   // S^1 (+indeg)
    launch_pdl(k_rescale1, nB, true, n);
    launch_pdl(k_prop_b, eB, true, src, dst, e);   // S^2
    launch_pdl(k_rescale2, nB, true, n);
    launch_pdl(k_prop1, eB, true, src, dst, e);    // S^3 (scalar)
    launch_pdl(k_out, nB, true, gid, out, n);
}

// round 17
// speedup vs baseline: 1.7924x; 1.2519x over previous
#include <cuda_runtime.h>
#include <cuda_fp16.h>

#define N_MAX 100000
#define HID 64
#define V_MAX 16384

// ---- persistent scratch (no allocation allowed) ----
__device__ int     g_outdeg[N_MAX];
__device__ float   g_nsrc[N_MAX];
__device__ float   g_ndst[N_MAX];
__device__ float   g_v[HID];        // W0 W1 W2 wreg
__device__ float   g_c0, g_c1, g_c2;
__device__ float   g_tdot[V_MAX];   // emb_table . v
__device__ __half2 g_P[N_MAX];      // prescaled (value, ones) pair — fp16
__device__ float4  g_A4[N_MAX];     // fp32 accumulator (x=val, y=ones, z=indeg)
__device__ float   g_Ps[N_MAX];     // prescaled scalar (final prop, fp32)
__device__ float   g_As[N_MAX];     // scalar accumulator (100k addrs)
__device__ float   g_s1[N_MAX];     // S^1 1

// vector REDs (sm_90+)
#define RED2(addr, a, b) \
    asm volatile("red.global.add.v2.f32 [%0], {%1, %2};" \
                 :: "l"(addr), "f"(a), "f"(b) : "memory")
#define RED4(addr, a, b, c, d) \
    asm volatile("red.global.add.v4.f32 [%0], {%1, %2, %3, %4};" \
                 :: "l"(addr), "f"(a), "f"(b), "f"(c), "f"(d) : "memory")

// ---------------------------------------------------------------
// K1: init + fold. Block 0 folds weights into g_v and bias scalars.
// ---------------------------------------------------------------
__global__ void k_init_fold(const float* __restrict__ Ws, const float* __restrict__ bs,
                            const float* __restrict__ wreg,
                            float* out, int n, int ng) {
    int i = blockIdx.x * blockDim.x + threadIdx.x;
    if (i < n) {
        g_outdeg[i] = 0;
        g_As[i] = 0.f;
        g_A4[i] = make_float4(0.f, 0.f, 0.f, 0.f);
    }
    if (i < ng) out[i] = 0.0f;

    if (blockIdx.x == 0) {
        __shared__ float sa[HID], sb[HID];
        int k = threadIdx.x;
        if (k < HID) {
            float s = 0.f;
            #pragma unroll 8
            for (int j = 0; j < HID; j++) s += Ws[2 * HID * HID + k * HID + j] * wreg[j];
            sa[k] = s;
        }
        __syncthreads();
        if (k < HID) {
            float s = 0.f;
            #pragma unroll 8
            for (int j = 0; j < HID; j++) s += Ws[1 * HID * HID + k * HID + j] * sa[j];
            sb[k] = s;
        }
        __syncthreads();
        if (k < HID) {
            float s = 0.f;
            #pragma unroll 8
            for (int j = 0; j < HID; j++) s += Ws[0 * HID * HID + k * HID + j] * sb[j];
            g_v[k] = s;
        }
        if (k == 0) {
            float c2 = 0.f, c1 = 0.f, c0 = 0.f;
            #pragma unroll 8
            for (int j = 0; j < HID; j++) {
                c2 += bs[2 * HID + j] * wreg[j];
                c1 += bs[1 * HID + j] * sa[j];
                c0 += bs[0 * HID + j] * sb[j];
            }
            g_c2 = c2; g_c1 = c1; g_c0 = c0;
        }
    }
}

// ---------------------------------------------------------------
// K2: OUT-degree only + tdot
// ---------------------------------------------------------------
__global__ void __launch_bounds__(256)
k_deg_tdot(const int* __restrict__ src, const float* __restrict__ emb,
           int e, int vocab) {
    cudaGridDependencySynchronize();
    int nt = gridDim.x * 256;
    int t = blockIdx.x * 256 + threadIdx.x;

    if (t < vocab * 16) {
        int w = t >> 4;
        int l = t & 15;
        float4 ev = __ldg((const float4*)emb + w * 16 + l);
        float4 vv = *(const float4*)&g_v[l * 4];
        float p = ev.x * vv.x + ev.y * vv.y + ev.z * vv.z + ev.w * vv.w;
        p += __shfl_xor_sync(0xffffffffu, p, 8);
        p += __shfl_xor_sync(0xffffffffu, p, 4);
        p += __shfl_xor_sync(0xffffffffu, p, 2);
        p += __shfl_xor_sync(0xffffffffu, p, 1);
        if (l == 0) g_tdot[w] = p;
    }

    int ng4 = e >> 2;
    #pragma unroll 2
    for (int j = t; j < ng4; j += nt) {
        int4 s = __ldcs((const int4*)src + j);
        atomicAdd(&g_outdeg[s.x], 1); atomicAdd(&g_outdeg[s.y], 1);
        atomicAdd(&g_outdeg[s.z], 1); atomicAdd(&g_outdeg[s.w], 1);
    }
    int i = (ng4 << 2) + t;
    if (i < e)
        atomicAdd(&g_outdeg[src[i]], 1);
}

// ---------------------------------------------------------------
// K3: ns + P0 = half2(z0*ns, ns)
// ---------------------------------------------------------------
__global__ void __launch_bounds__(256)
k_p0(const int* __restrict__ feats, int n) {
    cudaGridDependencySynchronize();
    int i = blockIdx.x * blockDim.x + threadIdx.x;
    if (i >= n) return;
    float ns = rsqrtf(fmaxf((float)g_outdeg[i], 1.0f));
    g_nsrc[i] = ns;
    float z0 = __ldg(&g_tdot[__ldg(&feats[i])]);
    g_P[i] = __floats2half2_rn(z0 * ns, ns);
}

// ---------------------------------------------------------------
// K4: prop S^1 — v4 RED carries {val, ones, 1(indeg), 0}
// ---------------------------------------------------------------
__global__ void __launch_bounds__(256)
k_prop_a(const int* __restrict__ src, const int* __restrict__ dst, int e) {
    cudaGridDependencySynchronize();
    int nt = gridDim.x * 256;
    int t = blockIdx.x * 256 + threadIdx.x;
    int ng4 = e >> 2;
    #pragma unroll 2
    for (int j = t; j < ng4; j += nt) {
        int4 s = __ldcs((const int4*)src + j);
        int4 d = __ldcs((const int4*)dst + j);
        float2 p0 = __half22float2(__ldg(&g_P[s.x]));
        float2 p1 = __half22float2(__ldg(&g_P[s.y]));
        float2 p2 = __half22float2(__ldg(&g_P[s.z]));
        float2 p3 = __half22float2(__ldg(&g_P[s.w]));
        RED4(&g_A4[d.x], p0.x, p0.y, 1.0f, 0.0f);
        RED4(&g_A4[d.y], p1.x, p1.y, 1.0f, 0.0f);
        RED4(&g_A4[d.z], p2.x, p2.y, 1.0f, 0.0f);
        RED4(&g_A4[d.w], p3.x, p3.y, 1.0f, 0.0f);
    }
    int i = (ng4 << 2) + t;
    if (i < e) {
        float2 p = __half22float2(__ldg(&g_P[src[i]]));
        RED4(&g_A4[dst[i]], p.x, p.y, 1.0f, 0.0f);
    }
}

// ---------------------------------------------------------------
// K5: rescale1: nd = rsqrt(max(indeg,1)); s1 = A.y*nd;
//     P = half2((A.x*nd)*ns, s1*ns); zero A.x/.y
// ---------------------------------------------------------------
__global__ void __launch_bounds__(256)
k_rescale1(int n) {
    cudaGridDependencySynchronize();
    int i = blockIdx.x * blockDim.x + threadIdx.x;
    if (i >= n) return;
    float4 A = g_A4[i];
    float nd = rsqrtf(fmaxf(A.z, 1.0f));
    float ns = g_nsrc[i];
    g_ndst[i] = nd;
    float u = A.x * nd, ss = A.y * nd;
    g_s1[i] = ss;
    g_P[i] = __floats2half2_rn(u * ns, ss * ns);
    *(float2*)&g_A4[i] = make_float2(0.f, 0.f);
}

// ---------------------------------------------------------------
// K6: prop S^2 — v2 RED into A4.x/.y
// ---------------------------------------------------------------
__global__ void __launch_bounds__(256)
k_prop_b(const int* __restrict__ src, const int* __restrict__ dst, int e) {
    cudaGridDependencySynchronize();
    int nt = gridDim.x * 256;
    int t = blockIdx.x * 256 + threadIdx.x;
    int ng4 = e >> 2;
    #pragma unroll 2
    for (int j = t; j < ng4; j += nt) {
        int4 s = __ldcs((const int4*)src + j);
        int4 d = __ldcs((const int4*)dst + j);
        float2 p0 = __half22float2(__ldg(&g_P[s.x]));
        float2 p1 = __half22float2(__ldg(&g_P[s.y]));
        float2 p2 = __half22float2(__ldg(&g_P[s.z]));
        float2 p3 = __half22float2(__ldg(&g_P[s.w]));
        RED2((float*)&g_A4[d.x], p0.x, p0.y);
        RED2((float*)&g_A4[d.y], p1.x, p1.y);
        RED2((float*)&g_A4[d.z], p2.x, p2.y);
        RED2((float*)&g_A4[d.w], p3.x, p3.y);
    }
    int i = (ng4 << 2) + t;
    if (i < e) {
        float2 p = __half22float2(__ldg(&g_P[src[i]]));
        RED2((float*)&g_A4[dst[i]], p.x, p.y);
    }
}

// ---------------------------------------------------------------
// K7: rescale2: Ps = A.x*nd*ns
// ---------------------------------------------------------------
__global__ void __launch_bounds__(256)
k_rescale2(int n) {
    cudaGridDependencySynchronize();
    int i = blockIdx.x * blockDim.x + threadIdx.x;
    if (i >= n) return;
    g_Ps[i] = g_A4[i].x * g_ndst[i] * g_nsrc[i];
}

// ---------------------------------------------------------------
// K8: final scalar prop: As[dst] += Ps[src]
// ---------------------------------------------------------------
__global__ void __launch_bounds__(256)
k_prop1(const int* __restrict__ src, const int* __restrict__ dst, int e) {
    cudaGridDependencySynchronize();
    int nt = gridDim.x * 256;
    int t = blockIdx.x * 256 + threadIdx.x;
    int ng4 = e >> 2;
    #pragma unroll 2
    for (int j = t; j < ng4; j += nt) {
        int4 s = __ldcs((const int4*)src + j);
        int4 d = __ldcs((const int4*)dst + j);
        atomicAdd(&g_As[d.x], __ldg(&g_Ps[s.x]));
        atomicAdd(&g_As[d.y], __ldg(&g_Ps[s.y]));
        atomicAdd(&g_As[d.z], __ldg(&g_Ps[s.z]));
        atomicAdd(&g_As[d.w], __ldg(&g_Ps[s.w]));
    }
    int i = (ng4 << 2) + t;
    if (i < e)
        atomicAdd(&g_As[dst[i]], __ldg(&g_Ps[src[i]]));
}

// ---------------------------------------------------------------
// K9: per-node combine + pooled output.
//     graph_ids are sorted -> most warps see ONE gid: warp-reduce,
//     single atomic. Mixed warps fall back per-lane (always correct).
// ---------------------------------------------------------------
__global__ void __launch_bounds__(256)
k_out(const int* __restrict__ gid, float* __restrict__ out, int n) {
    cudaGridDependencySynchronize();
    int i = blockIdx.x * blockDim.x + threadIdx.x;
    bool valid = (i < n);
    float val = 0.0f;
    int g = -1;
    if (valid) {
        float nd = g_ndst[i];
        float s2 = g_A4[i].y * nd;
        val = g_As[i] * nd + g_c0 * s2 + g_c1 * g_s1[i] + g_c2;
        g = __ldg(&gid[i]);
    }
    int g0 = __shfl_sync(0xffffffffu, g, 0);
    bool uniform = __all_sync(0xffffffffu, (g == g0) || !valid);
    if (uniform) {
        val += __shfl_xor_sync(0xffffffffu, val, 16);
        val += __shfl_xor_sync(0xffffffffu, val, 8);
        val += __shfl_xor_sync(0xffffffffu, val, 4);
        val += __shfl_xor_sync(0xffffffffu, val, 2);
        val += __shfl_xor_sync(0xffffffffu, val, 1);
        if ((threadIdx.x & 31) == 0 && g0 >= 0)
            atomicAdd(&out[g0], val);
    } else if (valid) {
        atomicAdd(&out[g], val);
    }
}

// ---------------------------------------------------------------
// PDL launch helper (programmatic stream serialization)
// ---------------------------------------------------------------
template <typename F, typename... Args>
static inline void launch_pdl(F kern, int grid, bool pdl, Args... args) {
    cudaLaunchConfig_t cfg = {};
    cfg.gridDim = dim3(grid, 1, 1);
    cfg.blockDim = dim3(256, 1, 1);
    cfg.dynamicSmemBytes = 0;
    cfg.stream = 0;
    cudaLaunchAttribute attr[1];
    attr[0].id = cudaLaunchAttributeProgrammaticStreamSerialization;
    attr[0].val.programmaticStreamSerializationAllowed = 1;
    cfg.attrs = attr;
    cfg.numAttrs = pdl ? 1 : 0;
    cudaLaunchKernelEx(&cfg, kern, args...);
}

// ---------------------------------------------------------------
extern "C" void kernel_launch(void* const* d_in, const int* in_sizes, int n_in,
                              void* d_out, int out_size)
{
    const int* feats = (const int*)d_in[0];
    const int* src   = (const int*)d_in[1];
    const int* dst   = (const int*)d_in[2];
    const int* gid   = (const int*)d_in[3];
    int k = 4;
    if (n_in >= 9 && in_sizes[4] == 1) k = 5;
    const float* emb  = (const float*)d_in[k];
    const float* Ws   = (const float*)d_in[k + 1];
    const float* bs   = (const float*)d_in[k + 2];
    const float* wreg = (const float*)d_in[k + 3];
    float* out = (float*)d_out;

    int n = in_sizes[0];
    int e = in_sizes[1];
    int ng = out_size;
    int vocab = in_sizes[k] / HID;

    int nB = (n + 255) / 256;

    int dev = 0, nsm = 148;
    cudaGetDevice(&dev);
    cudaDeviceGetAttribute(&nsm, cudaDevAttrMultiProcessorCount, dev);
    int eB = nsm * 8;
    int maxB = (e / 4 + 255) / 256;
    if (eB > maxB) eB = maxB;

    launch_pdl(k_init_fold, nB, false, Ws, bs, wreg, out, n, ng);
    launch_pdl(k_deg_tdot, eB, true, src, emb, e, vocab);
    launch_pdl(k_p0, nB, true, feats, n);
    launch_pdl(k_prop_a, eB, true, src, dst, e);   // S^1 (+indeg)
    launch_pdl(k_rescale1, nB, true, n);
    launch_pdl(k_prop_b, eB, true, src, dst, e);   // S^2
    launch_pdl(k_rescale2, nB, true, n);
    launch_pdl(k_prop1, eB, true, src, dst, e);    // S^3 (scalar)
    launch_pdl(k_out, nB, true, gid, out, n);
}